// round 4
// baseline (speedup 1.0000x reference)
#include <cuda_runtime.h>

#define NB 8
#define NS 1024
#define NE 512
#define NH 16
#define ND 32

typedef unsigned long long ull;

// Scratch for projected Q/K/V, layout [b, s, e] (e = h*32 + d)
__device__ float g_Q[NB * NS * NE];
__device__ float g_K[NB * NS * NE];
__device__ float g_V[NB * NS * NE];

// ---- packed fp32x2 helpers (sm_100+ PTX) ----------------------------------
__device__ __forceinline__ ull pack2(float x, float y) {
    ull d; asm("mov.b64 %0, {%1, %2};" : "=l"(d) : "f"(x), "f"(y)); return d;
}
__device__ __forceinline__ void unpack2(ull d, float& x, float& y) {
    asm("mov.b64 {%0, %1}, %2;" : "=f"(x), "=f"(y) : "l"(d));
}
__device__ __forceinline__ void fma2(ull& d, ull a, ull b) {
    asm("fma.rn.f32x2 %0, %1, %2, %0;" : "+l"(d) : "l"(a), "l"(b));
}
__device__ __forceinline__ void mul2(ull& d, ull a) {
    asm("mul.rn.f32x2 %0, %0, %1;" : "+l"(d) : "l"(a));
}

// ---------------------------------------------------------------------------
// Projection: Y = X @ W^T for W in {Wq, Wk, Wv}   (torch Linear convention)
// X: [8192, 512], W: [512, 512], Y: [8192, 512]
// 128x128 block tile, K-step 8, double-buffered smem, 8x8/thread f32x2 FMA.
// ---------------------------------------------------------------------------
__global__ __launch_bounds__(256, 2)
void proj_kernel(const float* __restrict__ X,
                 const float* __restrict__ Wq,
                 const float* __restrict__ Wk,
                 const float* __restrict__ Wv)
{
    __shared__ __align__(16) float As[2][8][132];
    __shared__ __align__(16) float Bs[2][8][132];

    const float* W = (blockIdx.z == 0) ? Wq : (blockIdx.z == 1) ? Wk : Wv;
    float* Y       = (blockIdx.z == 0) ? g_Q : (blockIdx.z == 1) ? g_K : g_V;

    const int m0 = blockIdx.x * 128;
    const int n0 = blockIdx.y * 128;
    const int tid = threadIdx.x;
    const int tx = tid & 15, ty = tid >> 4;
    const int lr = tid >> 1;            // 0..127
    const int lc = (tid & 1) << 2;      // 0 or 4

    const float* xa = X + (size_t)(m0 + lr) * NE + lc;
    const float* wa = W + (size_t)(n0 + lr) * NE + lc;

    ull acc2[8][4];
#pragma unroll
    for (int r = 0; r < 8; r++)
#pragma unroll
        for (int j = 0; j < 4; j++) acc2[r][j] = 0ull;

    // prologue: tile 0 -> buf 0
    {
        float4 a = *(const float4*)(xa);
        float4 b = *(const float4*)(wa);
        As[0][lc + 0][lr] = a.x; As[0][lc + 1][lr] = a.y;
        As[0][lc + 2][lr] = a.z; As[0][lc + 3][lr] = a.w;
        Bs[0][lc + 0][lr] = b.x; Bs[0][lc + 1][lr] = b.y;
        Bs[0][lc + 2][lr] = b.z; Bs[0][lc + 3][lr] = b.w;
    }
    __syncthreads();

#define PROJ_COMPUTE(BUF)                                                   \
    do {                                                                    \
        _Pragma("unroll")                                                   \
        for (int kk = 0; kk < 8; kk++) {                                    \
            float ar[8];                                                    \
            *(float4*)&ar[0] = *(const float4*)&As[BUF][kk][ty * 8];        \
            *(float4*)&ar[4] = *(const float4*)&As[BUF][kk][ty * 8 + 4];    \
            ull b2[4];                                                      \
            _Pragma("unroll")                                               \
            for (int j = 0; j < 4; j++)                                     \
                b2[j] = *(const ull*)&Bs[BUF][kk][tx * 8 + 2 * j];          \
            ull a2[8];                                                      \
            _Pragma("unroll")                                               \
            for (int r = 0; r < 8; r++) a2[r] = pack2(ar[r], ar[r]);        \
            _Pragma("unroll")                                               \
            for (int r = 0; r < 8; r++)                                     \
                _Pragma("unroll")                                           \
                for (int j = 0; j < 4; j++)                                 \
                    fma2(acc2[r][j], a2[r], b2[j]);                         \
        }                                                                   \
    } while (0)

    for (int k0 = 0; k0 < NE; k0 += 16) {
        // phase 0: compute buf0, prefetch k0+8 into buf1
        float4 a = *(const float4*)(xa + k0 + 8);
        float4 b = *(const float4*)(wa + k0 + 8);
        PROJ_COMPUTE(0);
        As[1][lc + 0][lr] = a.x; As[1][lc + 1][lr] = a.y;
        As[1][lc + 2][lr] = a.z; As[1][lc + 3][lr] = a.w;
        Bs[1][lc + 0][lr] = b.x; Bs[1][lc + 1][lr] = b.y;
        Bs[1][lc + 2][lr] = b.z; Bs[1][lc + 3][lr] = b.w;
        __syncthreads();

        // phase 1: compute buf1, prefetch k0+16 into buf0 (if any)
        if (k0 + 16 < NE) {
            a = *(const float4*)(xa + k0 + 16);
            b = *(const float4*)(wa + k0 + 16);
        }
        PROJ_COMPUTE(1);
        if (k0 + 16 < NE) {
            As[0][lc + 0][lr] = a.x; As[0][lc + 1][lr] = a.y;
            As[0][lc + 2][lr] = a.z; As[0][lc + 3][lr] = a.w;
            Bs[0][lc + 0][lr] = b.x; Bs[0][lc + 1][lr] = b.y;
            Bs[0][lc + 2][lr] = b.z; Bs[0][lc + 3][lr] = b.w;
            __syncthreads();
        }
    }
#undef PROJ_COMPUTE

#pragma unroll
    for (int r = 0; r < 8; r++) {
        float c[8];
#pragma unroll
        for (int j = 0; j < 4; j++) unpack2(acc2[r][j], c[2 * j], c[2 * j + 1]);
        float* yp = Y + (size_t)(m0 + ty * 8 + r) * NE + n0 + tx * 8;
        *(float4*)yp       = make_float4(c[0], c[1], c[2], c[3]);
        *(float4*)(yp + 4) = make_float4(c[4], c[5], c[6], c[7]);
    }
}

// ---------------------------------------------------------------------------
// Fused attention, flash-style. CTA = (b, h, 128-row q tile), 16 j-tiles of 64.
// Thread tile 8 rows x 4 cols; math packed f32x2 over row pairs.
// P stored row-pair-interleaved (ull) so PV loads packed operands directly.
// smem: qsT[32][132], ksT[32][68], ersT[32][196], vs[64][36], Psp[64][68] ull
// ---------------------------------------------------------------------------
__global__ __launch_bounds__(256, 2)
void attn_kernel(const float* __restrict__ Er, float* __restrict__ out)
{
    extern __shared__ float sm[];
    float* qsT  = sm;                     // 32*132 = 4224
    float* ksT  = qsT + 32 * 132;         // 32*68  = 2176
    float* ersT = ksT + 32 * 68;          // 32*196 = 6272
    float* vs   = ersT + 32 * 196;        // 64*36  = 2304
    ull*   Psp  = (ull*)(vs + 64 * 36);   // 64*68 ull = 34816 B

    const int b  = blockIdx.z;
    const int h  = blockIdx.y;
    const int i0 = blockIdx.x * 128;
    const int tid = threadIdx.x;
    const int tx = tid & 15, ty = tid >> 4;
    const float scale = 0.17677669529663687f;  // 1/sqrt(32)

    // Load Q tile (scaled) transposed: qsT[d][i], i = 0..127
    {
        const float* qg = g_Q + (size_t)(b * NS + i0) * NE + h * ND;
        for (int it = tid; it < 128 * 8; it += 256) {
            int r = it >> 3, d4 = (it & 7) << 2;
            float4 qv = *(const float4*)(qg + (size_t)r * NE + d4);
            qsT[(d4 + 0) * 132 + r] = qv.x * scale;
            qsT[(d4 + 1) * 132 + r] = qv.y * scale;
            qsT[(d4 + 2) * 132 + r] = qv.z * scale;
            qsT[(d4 + 3) * 132 + r] = qv.w * scale;
        }
    }

    float m[8], l[8];
    ull o2[4][2];   // o2[rp][dd]: low = row 2rp, high = row 2rp+1, dim tx*2+dd
#pragma unroll
    for (int r = 0; r < 8; r++) { m[r] = -1e30f; l[r] = 0.f; }
#pragma unroll
    for (int rp = 0; rp < 4; rp++) { o2[rp][0] = 0ull; o2[rp][1] = 0ull; }

    // per-thread Er window base: local idx = c - r + 7 in [0,10]
    const int ebase = 4 * tx - 8 * ty + 120;   // in [0, 180]

    for (int jt = 0; jt < 16; jt++) {
        const int j0 = jt * 64;
        __syncthreads();   // prior iteration done reading ks/vs/ers/Psp

        // Load K (transposed) and V (row-major) tiles
        const float* kg = g_K + (size_t)(b * NS + j0) * NE + h * ND;
        const float* vg = g_V + (size_t)(b * NS + j0) * NE + h * ND;
        for (int it = tid; it < 64 * 8; it += 256) {
            int r = it >> 3, d4 = (it & 7) << 2;
            float4 kv = *(const float4*)(kg + (size_t)r * NE + d4);
            ksT[(d4 + 0) * 68 + r] = kv.x;
            ksT[(d4 + 1) * 68 + r] = kv.y;
            ksT[(d4 + 2) * 68 + r] = kv.z;
            ksT[(d4 + 3) * 68 + r] = kv.w;
            float4 vv = *(const float4*)(vg + (size_t)r * NE + d4);
            *(float4*)&vs[r * 36 + d4] = vv;
        }
        // Er slice rows [s0, s0+190], transposed: ersT[d][t]
        const int s0 = j0 - i0 + 896;   // in [0, 1856]
        for (int it = tid; it < 191 * 8; it += 256) {
            int t = it >> 3, d4 = (it & 7) << 2;
            float4 ev = *(const float4*)(Er + (size_t)(s0 + t) * ND + d4);
            ersT[(d4 + 0) * 196 + t] = ev.x;
            ersT[(d4 + 1) * 196 + t] = ev.y;
            ersT[(d4 + 2) * 196 + t] = ev.z;
            ersT[(d4 + 3) * 196 + t] = ev.w;
        }
        __syncthreads();

        // Scores packed over row pairs: acc2[rp][c] = rows (2rp, 2rp+1), col tx*4+c
        ull acc2[4][4];
#pragma unroll
        for (int rp = 0; rp < 4; rp++)
#pragma unroll
            for (int c = 0; c < 4; c++) acc2[rp][c] = 0ull;

#pragma unroll 4
        for (int d = 0; d < 32; d++) {
            float qa[8], ka[4], ev[12];
            *(float4*)&qa[0] = *(const float4*)&qsT[d * 132 + ty * 8];
            *(float4*)&qa[4] = *(const float4*)&qsT[d * 132 + ty * 8 + 4];
            *(float4*)&ka[0] = *(const float4*)&ksT[d * 68 + tx * 4];
            *(float4*)&ev[0] = *(const float4*)&ersT[d * 196 + ebase];
            *(float4*)&ev[4] = *(const float4*)&ersT[d * 196 + ebase + 4];
            *(float4*)&ev[8] = *(const float4*)&ersT[d * 196 + ebase + 8];

            ull q2[4], k2[4], ep[11];
#pragma unroll
            for (int rp = 0; rp < 4; rp++) q2[rp] = pack2(qa[2 * rp], qa[2 * rp + 1]);
#pragma unroll
            for (int c = 0; c < 4; c++) k2[c] = pack2(ka[c], ka[c]);
#pragma unroll
            for (int i = 1; i <= 10; i++) ep[i] = pack2(ev[i], ev[i - 1]);

#pragma unroll
            for (int rp = 0; rp < 4; rp++)
#pragma unroll
                for (int c = 0; c < 4; c++) {
                    fma2(acc2[rp][c], q2[rp], k2[c]);
                    fma2(acc2[rp][c], q2[rp], ep[c - 2 * rp + 7]);
                }
        }

        // Online softmax per row; store P row-pair-interleaved into Psp
#pragma unroll
        for (int rp = 0; rp < 4; rp++) {
            float pv[2][4], corr[2];
#pragma unroll
            for (int rr = 0; rr < 2; rr++) {
                int r = 2 * rp + rr;
                float a0, a1, a2, a3, t;
                unpack2(acc2[rp][0], a0, t); if (rr) a0 = t;
                unpack2(acc2[rp][1], a1, t); if (rr) a1 = t;
                unpack2(acc2[rp][2], a2, t); if (rr) a2 = t;
                unpack2(acc2[rp][3], a3, t); if (rr) a3 = t;
                float tmax = fmaxf(fmaxf(a0, a1), fmaxf(a2, a3));
#pragma unroll
                for (int off = 8; off >= 1; off >>= 1)
                    tmax = fmaxf(tmax, __shfl_xor_sync(0xffffffffu, tmax, off));
                float mn = fmaxf(m[r], tmax);
                corr[rr] = __expf(m[r] - mn);
                float p0 = __expf(a0 - mn);
                float p1 = __expf(a1 - mn);
                float p2 = __expf(a2 - mn);
                float p3 = __expf(a3 - mn);
                float ps = (p0 + p1) + (p2 + p3);
#pragma unroll
                for (int off = 8; off >= 1; off >>= 1)
                    ps += __shfl_xor_sync(0xffffffffu, ps, off);
                l[r] = l[r] * corr[rr] + ps;
                m[r] = mn;
                pv[rr][0] = p0; pv[rr][1] = p1; pv[rr][2] = p2; pv[rr][3] = p3;
            }
            ull co2 = pack2(corr[0], corr[1]);
            mul2(o2[rp][0], co2);
            mul2(o2[rp][1], co2);
            ull* pd = &Psp[(ty * 4 + rp) * 68 + tx * 4];
            ((ulonglong2*)pd)[0] = make_ulonglong2(pack2(pv[0][0], pv[1][0]),
                                                  pack2(pv[0][1], pv[1][1]));
            ((ulonglong2*)pd)[1] = make_ulonglong2(pack2(pv[0][2], pv[1][2]),
                                                  pack2(pv[0][3], pv[1][3]));
        }
        __syncthreads();

        // O += P @ V, packed over row pairs (pm operands pre-packed in smem)
#pragma unroll 2
        for (int j = 0; j < 64; j += 4) {
            float va[4][2];
#pragma unroll
            for (int u = 0; u < 4; u++)
                *(float2*)&va[u][0] = *(const float2*)&vs[(j + u) * 36 + tx * 2];
            ull vb0[4], vb1[4];
#pragma unroll
            for (int u = 0; u < 4; u++) {
                vb0[u] = pack2(va[u][0], va[u][0]);
                vb1[u] = pack2(va[u][1], va[u][1]);
            }
#pragma unroll
            for (int rp = 0; rp < 4; rp++) {
                const ull* ps = &Psp[(ty * 4 + rp) * 68 + j];
                ulonglong2 pmA = ((const ulonglong2*)ps)[0];
                ulonglong2 pmB = ((const ulonglong2*)ps)[1];
                fma2(o2[rp][0], pmA.x, vb0[0]);
                fma2(o2[rp][1], pmA.x, vb1[0]);
                fma2(o2[rp][0], pmA.y, vb0[1]);
                fma2(o2[rp][1], pmA.y, vb1[1]);
                fma2(o2[rp][0], pmB.x, vb0[2]);
                fma2(o2[rp][1], pmB.x, vb1[2]);
                fma2(o2[rp][0], pmB.y, vb0[3]);
                fma2(o2[rp][1], pmB.y, vb1[3]);
            }
        }
    }

#pragma unroll
    for (int rp = 0; rp < 4; rp++) {
        float a0, a1, b0, b1;
        unpack2(o2[rp][0], a0, a1);
        unpack2(o2[rp][1], b0, b1);
        float inv0 = 1.0f / l[2 * rp];
        float inv1 = 1.0f / l[2 * rp + 1];
        size_t base = (size_t)(b * NS + i0 + ty * 8 + 2 * rp) * NE + h * ND + tx * 2;
        out[base]          = a0 * inv0;
        out[base + 1]      = b0 * inv0;
        out[base + NE]     = a1 * inv1;
        out[base + NE + 1] = b1 * inv1;
    }
}

// ---------------------------------------------------------------------------
extern "C" void kernel_launch(void* const* d_in, const int* in_sizes, int n_in,
                              void* d_out, int out_size)
{
    const float* x  = (const float*)d_in[0];
    const float* Wq = (const float*)d_in[1];
    const float* Wk = (const float*)d_in[2];
    const float* Wv = (const float*)d_in[3];
    const float* Er = (const float*)d_in[4];
    float* out = (float*)d_out;

    dim3 gp(64, 4, 3);             // 8192/128, 512/128, {Q,K,V}
    proj_kernel<<<gp, 256>>>(x, Wq, Wk, Wv);

    const int smem = (32 * 132 + 32 * 68 + 32 * 196 + 64 * 36) * 4 + 64 * 68 * 8; // 94720 B
    cudaFuncSetAttribute(attn_kernel, cudaFuncAttributeMaxDynamicSharedMemorySize, smem);
    dim3 ga(8, 16, 8);             // 1024/128 q-tiles, H, B
    attn_kernel<<<ga, 256, smem>>>(Er, out);
}

// round 7
// speedup vs baseline: 1.2106x; 1.2106x over previous
#include <cuda_runtime.h>
#include <cuda_bf16.h>
#include <cstdint>

#define NB 8
#define NS 1024
#define NE 512
#define NH 16
#define ND 32

// ---------------------------------------------------------------------------
// Scratch
// ---------------------------------------------------------------------------
__device__ float g_Q[NB * NS * NE];
__device__ float g_K[NB * NS * NE];
__device__ float g_V[NB * NS * NE];
__device__ __nv_bfloat16 g_Xhi[NB * NS * NE];
__device__ __nv_bfloat16 g_Xlo[NB * NS * NE];
__device__ __nv_bfloat16 g_Whi[3 * NE * NE];
__device__ __nv_bfloat16 g_Wlo[3 * NE * NE];

// ---------------------------------------------------------------------------
// warp-MMA helpers (non-arch-specific PTX: sm_80+ valid on base sm_103)
// ---------------------------------------------------------------------------
__device__ __forceinline__ uint32_t smem_u32(const void* p) {
    uint32_t a;
    asm("{ .reg .u64 t; cvta.to.shared.u64 t, %1; cvt.u32.u64 %0, t; }" : "=r"(a) : "l"(p));
    return a;
}
__device__ __forceinline__ void ldmatrix_x4(uint32_t& r0, uint32_t& r1, uint32_t& r2, uint32_t& r3,
                                            uint32_t addr) {
    asm volatile("ldmatrix.sync.aligned.m8n8.x4.shared.b16 {%0,%1,%2,%3}, [%4];"
                 : "=r"(r0), "=r"(r1), "=r"(r2), "=r"(r3) : "r"(addr));
}
__device__ __forceinline__ void mma_bf16(float& c0, float& c1, float& c2, float& c3,
                                         uint32_t a0, uint32_t a1, uint32_t a2, uint32_t a3,
                                         uint32_t b0, uint32_t b1) {
    asm volatile("mma.sync.aligned.m16n8k16.row.col.f32.bf16.bf16.f32 "
                 "{%0,%1,%2,%3}, {%4,%5,%6,%7}, {%8,%9}, {%0,%1,%2,%3};"
                 : "+f"(c0), "+f"(c1), "+f"(c2), "+f"(c3)
                 : "r"(a0), "r"(a1), "r"(a2), "r"(a3), "r"(b0), "r"(b1));
}

// ---------------------------------------------------------------------------
// Prep: fp32 -> (hi, lo) bf16 split. which: 0=X, 1..3=Wq/Wk/Wv
// ---------------------------------------------------------------------------
__global__ __launch_bounds__(256)
void prep_kernel(const float* __restrict__ src, int which, int n)
{
    int i = (blockIdx.x * 256 + threadIdx.x) * 4;
    if (i >= n) return;
    __nv_bfloat16* hi;
    __nv_bfloat16* lo;
    if (which == 0) { hi = g_Xhi; lo = g_Xlo; }
    else            { hi = g_Whi + (which - 1) * NE * NE; lo = g_Wlo + (which - 1) * NE * NE; }
    float4 v = *(const float4*)(src + i);
    float vv[4] = {v.x, v.y, v.z, v.w};
    __nv_bfloat16 hh[4], ll[4];
#pragma unroll
    for (int j = 0; j < 4; j++) {
        hh[j] = __float2bfloat16(vv[j]);
        ll[j] = __float2bfloat16(vv[j] - __bfloat162float(hh[j]));
    }
    *(uint2*)(hi + i) = *(uint2*)hh;
    *(uint2*)(lo + i) = *(uint2*)ll;
}

// ---------------------------------------------------------------------------
// Projection GEMM via mma.sync bf16x3: Y = X @ W^T (fp32 result).
// CTA 128(M) x 128(N), 256 thr = 8 warps (4 m-slabs x 2 n-slabs), warp 32x64.
// K: 3 segments (Xhi*Whi, Xhi*Wlo, Xlo*Whi) x 512, chunk 32, double-buffered.
// smem rows padded to 40 bf16 (80B) -> conflict-free ldmatrix.
// ---------------------------------------------------------------------------
__global__ __launch_bounds__(256, 2)
void proj_mma_kernel()
{
    __shared__ __align__(16) __nv_bfloat16 As[2][128 * 40];
    __shared__ __align__(16) __nv_bfloat16 Bs[2][128 * 40];

    const int tid  = threadIdx.x;
    const int wid  = tid >> 5;
    const int lane = tid & 31;
    const int wm   = (wid & 3) * 32;     // warp m-offset in tile
    const int wn   = (wid >> 2) * 64;    // warp n-offset in tile

    const int m0 = blockIdx.x * 128;
    const int n0 = blockIdx.y * 128;
    const int z  = blockIdx.z;
    const __nv_bfloat16* Whi = g_Whi + z * NE * NE;
    const __nv_bfloat16* Wlo = g_Wlo + z * NE * NE;
    float* Y = (z == 0) ? g_Q : (z == 1) ? g_K : g_V;

    // staging assignment: element e in [0,512): row = e>>2, kq = e&3 (8 bf16 per uint4)
    const int e0 = tid, e1 = tid + 256;
    const int r0s = e0 >> 2, q0s = e0 & 3;
    const int r1s = e1 >> 2, q1s = e1 & 3;

    float acc[2][8][4];
#pragma unroll
    for (int i = 0; i < 2; i++)
#pragma unroll
        for (int j = 0; j < 8; j++)
#pragma unroll
            for (int c = 0; c < 4; c++) acc[i][j][c] = 0.f;

    // ldmatrix source addresses (per-warp fragment bases)
    // A frag at (wm + rf*16): row = base + (lane&15), col = kc + (lane>>4)*8
    // B frag pair at (wn + nb*16): row = base + (lane&7) + (lane>>4)*8, col = kc + ((lane>>3)&1)*8
    const int a_row = (lane & 15);
    const int a_col = (lane >> 4) * 8;
    const int b_row = (lane & 7) + (lane >> 4) * 8;
    const int b_col = ((lane >> 3) & 1) * 8;

    const uint32_t as_base = smem_u32(As);
    const uint32_t bs_base = smem_u32(Bs);

    // prologue: stage chunk 0 (seg 0, k0 = 0)
    {
        uint4 va0 = *(const uint4*)(g_Xhi + (size_t)(m0 + r0s) * NE + q0s * 8);
        uint4 va1 = *(const uint4*)(g_Xhi + (size_t)(m0 + r1s) * NE + q1s * 8);
        uint4 vb0 = *(const uint4*)(Whi + (size_t)(n0 + r0s) * NE + q0s * 8);
        uint4 vb1 = *(const uint4*)(Whi + (size_t)(n0 + r1s) * NE + q1s * 8);
        *(uint4*)&As[0][r0s * 40 + q0s * 8] = va0;
        *(uint4*)&As[0][r1s * 40 + q1s * 8] = va1;
        *(uint4*)&Bs[0][r0s * 40 + q0s * 8] = vb0;
        *(uint4*)&Bs[0][r1s * 40 + q1s * 8] = vb1;
    }
    __syncthreads();

    for (int it = 0; it < 48; it++) {
        const int cur = it & 1;
        // prefetch next chunk into registers
        uint4 va0, va1, vb0, vb1;
        if (it + 1 < 48) {
            const int nit = it + 1;
            const int seg = nit >> 4;
            const int k0  = (nit & 15) * 32;
            const __nv_bfloat16* Asrc = (seg < 2) ? g_Xhi : g_Xlo;
            const __nv_bfloat16* Bsrc = (seg == 1) ? Wlo : Whi;
            va0 = *(const uint4*)(Asrc + (size_t)(m0 + r0s) * NE + k0 + q0s * 8);
            va1 = *(const uint4*)(Asrc + (size_t)(m0 + r1s) * NE + k0 + q1s * 8);
            vb0 = *(const uint4*)(Bsrc + (size_t)(n0 + r0s) * NE + k0 + q0s * 8);
            vb1 = *(const uint4*)(Bsrc + (size_t)(n0 + r1s) * NE + k0 + q1s * 8);
        }

        // compute on current buffer: 2 k16-steps
        const uint32_t abuf = as_base + cur * (128 * 40 * 2);
        const uint32_t bbuf = bs_base + cur * (128 * 40 * 2);
#pragma unroll
        for (int kc = 0; kc < 32; kc += 16) {
            uint32_t af[2][4];
#pragma unroll
            for (int rf = 0; rf < 2; rf++) {
                uint32_t addr = abuf + ((wm + rf * 16 + a_row) * 40 + kc + a_col) * 2;
                ldmatrix_x4(af[rf][0], af[rf][1], af[rf][2], af[rf][3], addr);
            }
            uint32_t bf[8][2];
#pragma unroll
            for (int nb = 0; nb < 4; nb++) {
                uint32_t addr = bbuf + ((wn + nb * 16 + b_row) * 40 + kc + b_col) * 2;
                ldmatrix_x4(bf[nb * 2][0], bf[nb * 2][1], bf[nb * 2 + 1][0], bf[nb * 2 + 1][1], addr);
            }
#pragma unroll
            for (int rf = 0; rf < 2; rf++)
#pragma unroll
                for (int nf = 0; nf < 8; nf++)
                    mma_bf16(acc[rf][nf][0], acc[rf][nf][1], acc[rf][nf][2], acc[rf][nf][3],
                             af[rf][0], af[rf][1], af[rf][2], af[rf][3],
                             bf[nf][0], bf[nf][1]);
        }

        if (it + 1 < 48) {
            const int nxt = cur ^ 1;
            *(uint4*)&As[nxt][r0s * 40 + q0s * 8] = va0;
            *(uint4*)&As[nxt][r1s * 40 + q1s * 8] = va1;
            *(uint4*)&Bs[nxt][r0s * 40 + q0s * 8] = vb0;
            *(uint4*)&Bs[nxt][r1s * 40 + q1s * 8] = vb1;
            __syncthreads();
        }
    }

    // epilogue: c-frag mapping (m16n8): c0,c1 -> row lane/4, col (lane&3)*2; c2,c3 -> row+8
    const int er = lane >> 2, ec = (lane & 3) * 2;
#pragma unroll
    for (int rf = 0; rf < 2; rf++)
#pragma unroll
        for (int nf = 0; nf < 8; nf++) {
            size_t base = (size_t)(m0 + wm + rf * 16 + er) * NE + n0 + wn + nf * 8 + ec;
            *(float2*)(Y + base)          = make_float2(acc[rf][nf][0], acc[rf][nf][1]);
            *(float2*)(Y + base + 8 * NE) = make_float2(acc[rf][nf][2], acc[rf][nf][3]);
        }
}

// ---------------------------------------------------------------------------
// Fused attention (round-3 scalar fp32): flash-style online softmax.
// CTA = (b, h, 128-row q tile), 16 j-tiles of 64. Thread tile 8x4.
// ---------------------------------------------------------------------------
__global__ __launch_bounds__(256, 2)
void attn_kernel(const float* __restrict__ Er, float* __restrict__ out)
{
    extern __shared__ float sm[];
    float* qsT  = sm;                     // 32*132
    float* ksT  = qsT + 32 * 132;         // 32*68
    float* ersT = ksT + 32 * 68;          // 32*196
    float* vs   = ersT + 32 * 196;        // 64*36
    float* Ps   = vs + 64 * 36;           // 128*68

    const int b  = blockIdx.z;
    const int h  = blockIdx.y;
    const int i0 = blockIdx.x * 128;
    const int tid = threadIdx.x;
    const int tx = tid & 15, ty = tid >> 4;
    const float scale = 0.17677669529663687f;  // 1/sqrt(32)

    {
        const float* qg = g_Q + (size_t)(b * NS + i0) * NE + h * ND;
        for (int it = tid; it < 128 * 8; it += 256) {
            int r = it >> 3, d4 = (it & 7) << 2;
            float4 qv = *(const float4*)(qg + (size_t)r * NE + d4);
            qsT[(d4 + 0) * 132 + r] = qv.x * scale;
            qsT[(d4 + 1) * 132 + r] = qv.y * scale;
            qsT[(d4 + 2) * 132 + r] = qv.z * scale;
            qsT[(d4 + 3) * 132 + r] = qv.w * scale;
        }
    }

    float m[8], l[8], o[8][2];
#pragma unroll
    for (int r = 0; r < 8; r++) { m[r] = -1e30f; l[r] = 0.f; o[r][0] = 0.f; o[r][1] = 0.f; }

    const int ebase = 4 * tx - 8 * ty + 120;   // in [0, 180]

    for (int jt = 0; jt < 16; jt++) {
        const int j0 = jt * 64;
        __syncthreads();

        const float* kg = g_K + (size_t)(b * NS + j0) * NE + h * ND;
        const float* vg = g_V + (size_t)(b * NS + j0) * NE + h * ND;
        for (int it = tid; it < 64 * 8; it += 256) {
            int r = it >> 3, d4 = (it & 7) << 2;
            float4 kv = *(const float4*)(kg + (size_t)r * NE + d4);
            ksT[(d4 + 0) * 68 + r] = kv.x;
            ksT[(d4 + 1) * 68 + r] = kv.y;
            ksT[(d4 + 2) * 68 + r] = kv.z;
            ksT[(d4 + 3) * 68 + r] = kv.w;
            float4 vv = *(const float4*)(vg + (size_t)r * NE + d4);
            *(float4*)&vs[r * 36 + d4] = vv;
        }
        const int s0 = j0 - i0 + 896;   // in [0, 1856]
        for (int it = tid; it < 191 * 8; it += 256) {
            int t = it >> 3, d4 = (it & 7) << 2;
            float4 ev = *(const float4*)(Er + (size_t)(s0 + t) * ND + d4);
            ersT[(d4 + 0) * 196 + t] = ev.x;
            ersT[(d4 + 1) * 196 + t] = ev.y;
            ersT[(d4 + 2) * 196 + t] = ev.z;
            ersT[(d4 + 3) * 196 + t] = ev.w;
        }
        __syncthreads();

        float acc[8][4];
#pragma unroll
        for (int r = 0; r < 8; r++)
#pragma unroll
            for (int c = 0; c < 4; c++) acc[r][c] = 0.f;

#pragma unroll 4
        for (int d = 0; d < 32; d++) {
            float qa[8], ka[4], ev[12];
            *(float4*)&qa[0] = *(const float4*)&qsT[d * 132 + ty * 8];
            *(float4*)&qa[4] = *(const float4*)&qsT[d * 132 + ty * 8 + 4];
            *(float4*)&ka[0] = *(const float4*)&ksT[d * 68 + tx * 4];
            *(float4*)&ev[0] = *(const float4*)&ersT[d * 196 + ebase];
            *(float4*)&ev[4] = *(const float4*)&ersT[d * 196 + ebase + 4];
            *(float4*)&ev[8] = *(const float4*)&ersT[d * 196 + ebase + 8];
#pragma unroll
            for (int r = 0; r < 8; r++)
#pragma unroll
                for (int c = 0; c < 4; c++)
                    acc[r][c] = fmaf(qa[r], ka[c] + ev[c - r + 7], acc[r][c]);
        }

#pragma unroll
        for (int r = 0; r < 8; r++) {
            float tmax = fmaxf(fmaxf(acc[r][0], acc[r][1]), fmaxf(acc[r][2], acc[r][3]));
#pragma unroll
            for (int off = 8; off >= 1; off >>= 1)
                tmax = fmaxf(tmax, __shfl_xor_sync(0xffffffffu, tmax, off));
            float mn = fmaxf(m[r], tmax);
            float corr = __expf(m[r] - mn);
            float p0 = __expf(acc[r][0] - mn);
            float p1 = __expf(acc[r][1] - mn);
            float p2 = __expf(acc[r][2] - mn);
            float p3 = __expf(acc[r][3] - mn);
            float ps = (p0 + p1) + (p2 + p3);
#pragma unroll
            for (int off = 8; off >= 1; off >>= 1)
                ps += __shfl_xor_sync(0xffffffffu, ps, off);
            l[r] = l[r] * corr + ps;
            m[r] = mn;
            o[r][0] *= corr;
            o[r][1] *= corr;
            *(float4*)&Ps[(ty * 8 + r) * 68 + tx * 4] = make_float4(p0, p1, p2, p3);
        }
        __syncthreads();

#pragma unroll 2
        for (int j = 0; j < 64; j += 4) {
            float va[4][2];
#pragma unroll
            for (int u = 0; u < 4; u++)
                *(float2*)&va[u][0] = *(const float2*)&vs[(j + u) * 36 + tx * 2];
#pragma unroll
            for (int r = 0; r < 8; r++) {
                float4 pm = *(const float4*)&Ps[(ty * 8 + r) * 68 + j];
                o[r][0] = fmaf(pm.x, va[0][0], o[r][0]);
                o[r][1] = fmaf(pm.x, va[0][1], o[r][1]);
                o[r][0] = fmaf(pm.y, va[1][0], o[r][0]);
                o[r][1] = fmaf(pm.y, va[1][1], o[r][1]);
                o[r][0] = fmaf(pm.z, va[2][0], o[r][0]);
                o[r][1] = fmaf(pm.z, va[2][1], o[r][1]);
                o[r][0] = fmaf(pm.w, va[3][0], o[r][0]);
                o[r][1] = fmaf(pm.w, va[3][1], o[r][1]);
            }
        }
    }

#pragma unroll
    for (int r = 0; r < 8; r++) {
        float inv = 1.0f / l[r];
        size_t oidx = (size_t)(b * NS + i0 + ty * 8 + r) * NE + h * ND + tx * 2;
        out[oidx]     = o[r][0] * inv;
        out[oidx + 1] = o[r][1] * inv;
    }
}

// ---------------------------------------------------------------------------
extern "C" void kernel_launch(void* const* d_in, const int* in_sizes, int n_in,
                              void* d_out, int out_size)
{
    const float* x  = (const float*)d_in[0];
    const float* Wq = (const float*)d_in[1];
    const float* Wk = (const float*)d_in[2];
    const float* Wv = (const float*)d_in[3];
    const float* Er = (const float*)d_in[4];
    float* out = (float*)d_out;

    // split fp32 -> bf16 hi/lo
    prep_kernel<<<(NB * NS * NE) / 1024, 256>>>(x, 0, NB * NS * NE);
    prep_kernel<<<(NE * NE) / 1024, 256>>>(Wq, 1, NE * NE);
    prep_kernel<<<(NE * NE) / 1024, 256>>>(Wk, 2, NE * NE);
    prep_kernel<<<(NE * NE) / 1024, 256>>>(Wv, 3, NE * NE);

    // projections on tensor pipe (warp mma.sync bf16x3)
    dim3 gg(64, 4, 3);             // M-tiles (8192/128), N-tiles (512/128), {Q,K,V}
    proj_mma_kernel<<<gg, 256>>>();

    // attention
    const int asmem = (32 * 132 + 32 * 68 + 32 * 196 + 64 * 36 + 128 * 68) * (int)sizeof(float);
    cudaFuncSetAttribute(attn_kernel, cudaFuncAttributeMaxDynamicSharedMemorySize, asmem);
    dim3 ga(8, 16, 8);             // q-tiles, H, B
    attn_kernel<<<ga, 256, asmem>>>(Er, out);
}

// round 11
// speedup vs baseline: 1.8736x; 1.5476x over previous
#include <cuda_runtime.h>
#include <cuda_bf16.h>
#include <cstdint>

#define NB 8
#define NS 1024
#define NE 512
#define NH 16
#define ND 32

// ---------------------------------------------------------------------------
// Scratch (all bf16 hi/lo pairs)
// ---------------------------------------------------------------------------
__device__ __nv_bfloat16 g_Xhi[NB * NS * NE];
__device__ __nv_bfloat16 g_Xlo[NB * NS * NE];
__device__ __nv_bfloat16 g_Whi[3 * NE * NE];
__device__ __nv_bfloat16 g_Wlo[3 * NE * NE];
// head-separated [b][h][s][d]
__device__ __nv_bfloat16 g_Qhi[NB * NH * NS * ND];
__device__ __nv_bfloat16 g_Qlo[NB * NH * NS * ND];
__device__ __nv_bfloat16 g_Khi[NB * NH * NS * ND];
__device__ __nv_bfloat16 g_Klo[NB * NH * NS * ND];
__device__ __nv_bfloat16 g_Vhi[NB * NH * NS * ND];
__device__ __nv_bfloat16 g_Vlo[NB * NH * NS * ND];
// Er padded to 2048 rows (row 2047 zero)
__device__ __nv_bfloat16 g_Erhi[2048 * ND];
__device__ __nv_bfloat16 g_Erlo[2048 * ND];

// ---------------------------------------------------------------------------
// helpers
// ---------------------------------------------------------------------------
__device__ __forceinline__ uint32_t smem_u32(const void* p) {
    uint32_t a;
    asm("{ .reg .u64 t; cvta.to.shared.u64 t, %1; cvt.u32.u64 %0, t; }" : "=r"(a) : "l"(p));
    return a;
}
__device__ __forceinline__ void ldmatrix_x4(uint32_t& r0, uint32_t& r1, uint32_t& r2, uint32_t& r3,
                                            uint32_t addr) {
    asm volatile("ldmatrix.sync.aligned.m8n8.x4.shared.b16 {%0,%1,%2,%3}, [%4];"
                 : "=r"(r0), "=r"(r1), "=r"(r2), "=r"(r3) : "r"(addr));
}
__device__ __forceinline__ void mma_bf16(float* c,
                                         const uint32_t* a,
                                         uint32_t b0, uint32_t b1) {
    asm volatile("mma.sync.aligned.m16n8k16.row.col.f32.bf16.bf16.f32 "
                 "{%0,%1,%2,%3}, {%4,%5,%6,%7}, {%8,%9}, {%0,%1,%2,%3};"
                 : "+f"(c[0]), "+f"(c[1]), "+f"(c[2]), "+f"(c[3])
                 : "r"(a[0]), "r"(a[1]), "r"(a[2]), "r"(a[3]), "r"(b0), "r"(b1));
}
// pack two fp32 into bf16x2: low half = lo, high half = hi
__device__ __forceinline__ uint32_t cvt2bf(float lo, float hi) {
    uint32_t r;
    asm("cvt.rn.bf16x2.f32 %0, %1, %2;" : "=r"(r) : "f"(hi), "f"(lo));
    return r;
}
__device__ __forceinline__ float bfres(float x) {
    return x - __bfloat162float(__float2bfloat16(x));
}

// ---------------------------------------------------------------------------
// Prep: fp32 -> (hi, lo) bf16 split. which: 0=X, 1..3=Wq/Wk/Wv
// ---------------------------------------------------------------------------
__global__ __launch_bounds__(256)
void prep_kernel(const float* __restrict__ src, int which, int n)
{
    int i = (blockIdx.x * 256 + threadIdx.x) * 4;
    if (i >= n) return;
    __nv_bfloat16* hi;
    __nv_bfloat16* lo;
    if (which == 0) { hi = g_Xhi; lo = g_Xlo; }
    else            { hi = g_Whi + (which - 1) * NE * NE; lo = g_Wlo + (which - 1) * NE * NE; }
    float4 v = *(const float4*)(src + i);
    float vv[4] = {v.x, v.y, v.z, v.w};
    __nv_bfloat16 hh[4], ll[4];
#pragma unroll
    for (int j = 0; j < 4; j++) {
        hh[j] = __float2bfloat16(vv[j]);
        ll[j] = __float2bfloat16(vv[j] - __bfloat162float(hh[j]));
    }
    *(uint2*)(hi + i) = *(uint2*)hh;
    *(uint2*)(lo + i) = *(uint2*)ll;
}

// Er split with zero-padded row 2047
__global__ __launch_bounds__(256)
void prep_er(const float* __restrict__ Er)
{
    int i = (blockIdx.x * 256 + threadIdx.x) * 4;
    if (i >= 2048 * ND) return;
    float4 v = make_float4(0.f, 0.f, 0.f, 0.f);
    if (i < 2047 * ND) v = *(const float4*)(Er + i);
    float vv[4] = {v.x, v.y, v.z, v.w};
    __nv_bfloat16 hh[4], ll[4];
#pragma unroll
    for (int j = 0; j < 4; j++) {
        hh[j] = __float2bfloat16(vv[j]);
        ll[j] = __float2bfloat16(vv[j] - __bfloat162float(hh[j]));
    }
    *(uint2*)(g_Erhi + i) = *(uint2*)hh;
    *(uint2*)(g_Erlo + i) = *(uint2*)ll;
}

// ---------------------------------------------------------------------------
// Projection GEMM via mma.sync bf16x3: Y = X @ W^T.
// Epilogue writes head-separated bf16 hi/lo Q/K/V (Q pre-scaled by 1/sqrt(D)).
// ---------------------------------------------------------------------------
__global__ __launch_bounds__(256, 2)
void proj_mma_kernel()
{
    __shared__ __align__(16) __nv_bfloat16 As[2][128 * 40];
    __shared__ __align__(16) __nv_bfloat16 Bs[2][128 * 40];

    const int tid  = threadIdx.x;
    const int wid  = tid >> 5;
    const int lane = tid & 31;
    const int wm   = (wid & 3) * 32;
    const int wn   = (wid >> 2) * 64;

    const int m0 = blockIdx.x * 128;
    const int n0 = blockIdx.y * 128;
    const int z  = blockIdx.z;
    const __nv_bfloat16* Whi = g_Whi + z * NE * NE;
    const __nv_bfloat16* Wlo = g_Wlo + z * NE * NE;

    const int e0 = tid, e1 = tid + 256;
    const int r0s = e0 >> 2, q0s = e0 & 3;
    const int r1s = e1 >> 2, q1s = e1 & 3;

    float acc[2][8][4];
#pragma unroll
    for (int i = 0; i < 2; i++)
#pragma unroll
        for (int j = 0; j < 8; j++)
#pragma unroll
            for (int c = 0; c < 4; c++) acc[i][j][c] = 0.f;

    const int a_row = (lane & 15);
    const int a_col = (lane >> 4) * 8;
    const int b_row = (lane & 7) + (lane >> 4) * 8;
    const int b_col = ((lane >> 3) & 1) * 8;

    const uint32_t as_base = smem_u32(As);
    const uint32_t bs_base = smem_u32(Bs);

    {
        uint4 va0 = *(const uint4*)(g_Xhi + (size_t)(m0 + r0s) * NE + q0s * 8);
        uint4 va1 = *(const uint4*)(g_Xhi + (size_t)(m0 + r1s) * NE + q1s * 8);
        uint4 vb0 = *(const uint4*)(Whi + (size_t)(n0 + r0s) * NE + q0s * 8);
        uint4 vb1 = *(const uint4*)(Whi + (size_t)(n0 + r1s) * NE + q1s * 8);
        *(uint4*)&As[0][r0s * 40 + q0s * 8] = va0;
        *(uint4*)&As[0][r1s * 40 + q1s * 8] = va1;
        *(uint4*)&Bs[0][r0s * 40 + q0s * 8] = vb0;
        *(uint4*)&Bs[0][r1s * 40 + q1s * 8] = vb1;
    }
    __syncthreads();

    for (int it = 0; it < 48; it++) {
        const int cur = it & 1;
        uint4 va0, va1, vb0, vb1;
        if (it + 1 < 48) {
            const int nit = it + 1;
            const int seg = nit >> 4;
            const int k0  = (nit & 15) * 32;
            const __nv_bfloat16* Asrc = (seg < 2) ? g_Xhi : g_Xlo;
            const __nv_bfloat16* Bsrc = (seg == 1) ? Wlo : Whi;
            va0 = *(const uint4*)(Asrc + (size_t)(m0 + r0s) * NE + k0 + q0s * 8);
            va1 = *(const uint4*)(Asrc + (size_t)(m0 + r1s) * NE + k0 + q1s * 8);
            vb0 = *(const uint4*)(Bsrc + (size_t)(n0 + r0s) * NE + k0 + q0s * 8);
            vb1 = *(const uint4*)(Bsrc + (size_t)(n0 + r1s) * NE + k0 + q1s * 8);
        }

        const uint32_t abuf = as_base + cur * (128 * 40 * 2);
        const uint32_t bbuf = bs_base + cur * (128 * 40 * 2);
#pragma unroll
        for (int kc = 0; kc < 32; kc += 16) {
            uint32_t af[2][4];
#pragma unroll
            for (int rf = 0; rf < 2; rf++) {
                uint32_t addr = abuf + ((wm + rf * 16 + a_row) * 40 + kc + a_col) * 2;
                ldmatrix_x4(af[rf][0], af[rf][1], af[rf][2], af[rf][3], addr);
            }
            uint32_t bf[8][2];
#pragma unroll
            for (int nb = 0; nb < 4; nb++) {
                uint32_t addr = bbuf + ((wn + nb * 16 + b_row) * 40 + kc + b_col) * 2;
                ldmatrix_x4(bf[nb * 2][0], bf[nb * 2][1], bf[nb * 2 + 1][0], bf[nb * 2 + 1][1], addr);
            }
#pragma unroll
            for (int rf = 0; rf < 2; rf++)
#pragma unroll
                for (int nf = 0; nf < 8; nf++)
                    mma_bf16(acc[rf][nf], af[rf], bf[nf][0], bf[nf][1]);
        }

        if (it + 1 < 48) {
            const int nxt = cur ^ 1;
            *(uint4*)&As[nxt][r0s * 40 + q0s * 8] = va0;
            *(uint4*)&As[nxt][r1s * 40 + q1s * 8] = va1;
            *(uint4*)&Bs[nxt][r0s * 40 + q0s * 8] = vb0;
            *(uint4*)&Bs[nxt][r1s * 40 + q1s * 8] = vb1;
            __syncthreads();
        }
    }

    // epilogue -> head-separated bf16 hi/lo
    const float qs = (z == 0) ? 0.17677669529663687f : 1.0f;
    __nv_bfloat16* Dhi = (z == 0) ? g_Qhi : (z == 1) ? g_Khi : g_Vhi;
    __nv_bfloat16* Dlo = (z == 0) ? g_Qlo : (z == 1) ? g_Klo : g_Vlo;
    const int er = lane >> 2, ec = (lane & 3) * 2;
#pragma unroll
    for (int rf = 0; rf < 2; rf++)
#pragma unroll
        for (int nf = 0; nf < 8; nf++) {
            const int col = n0 + wn + nf * 8 + ec;
            const int hh = col >> 5, d = col & 31;
#pragma unroll
            for (int rr = 0; rr < 2; rr++) {
                const int row = m0 + wm + rf * 16 + er + rr * 8;
                const int bb = row >> 10, s = row & 1023;
                const size_t idx = (((size_t)bb * NH + hh) * NS + s) * ND + d;
                const float v0 = acc[rf][nf][rr * 2] * qs;
                const float v1 = acc[rf][nf][rr * 2 + 1] * qs;
                *(uint32_t*)(Dhi + idx) = cvt2bf(v0, v1);
                *(uint32_t*)(Dlo + idx) = cvt2bf(bfres(v0), bfres(v1));
            }
        }
}

// ---------------------------------------------------------------------------
// Tensor-core attention: CTA = (b, h, 128-q), 8 warps x 16 rows, j-tiles of 64.
// Scores = QK^T + skew(Q @ ErSlice^T), all bf16x3. Flash softmax in fp32.
// P re-packed in-register (c-frag == a-frag layout) -> PV bf16x3.
// ---------------------------------------------------------------------------
__global__ __launch_bounds__(256)
void attn_mma_kernel(float* __restrict__ out)
{
    extern __shared__ __align__(16) char smem[];
    __nv_bfloat16* sQhi = (__nv_bfloat16*)smem;         // 128*40
    __nv_bfloat16* sQlo = sQhi + 128 * 40;
    __nv_bfloat16* sKhi = sQlo + 128 * 40;              // 64*40
    __nv_bfloat16* sKlo = sKhi + 64 * 40;
    __nv_bfloat16* sVhi = sKlo + 64 * 40;               // 32*72 (V^T)
    __nv_bfloat16* sVlo = sVhi + 32 * 72;
    __nv_bfloat16* sEhi = sVlo + 32 * 72;               // 192*40
    __nv_bfloat16* sElo = sEhi + 192 * 40;
    float*         sR   = (float*)(sElo + 192 * 40);    // 128*72 fp32

    const int tid = threadIdx.x, wid = tid >> 5, lane = tid & 31;
    const int b = blockIdx.z, h = blockIdx.y, i0 = blockIdx.x * 128;
    const size_t bh = (size_t)(b * NH + h) * NS;

    const int a_row = lane & 15, a_col = (lane >> 4) * 8;
    const int b_row = (lane & 7) + ((lane >> 4) << 3), b_col = ((lane >> 3) & 1) * 8;
    const int r0 = lane >> 2, cq = (lane & 3) * 2;
    const int ebase = 112 - 16 * wid;

    const uint32_t uQhi = smem_u32(sQhi), uQlo = smem_u32(sQlo);
    const uint32_t uKhi = smem_u32(sKhi), uKlo = smem_u32(sKlo);
    const uint32_t uVhi = smem_u32(sVhi), uVlo = smem_u32(sVlo);
    const uint32_t uEhi = smem_u32(sEhi), uElo = smem_u32(sElo);

    // stage Q once
    for (int it = tid; it < 512; it += 256) {
        int r = it >> 2, c8 = (it & 3) * 8;
        *(uint4*)&sQhi[r * 40 + c8] = *(const uint4*)(g_Qhi + (bh + i0 + r) * ND + c8);
        *(uint4*)&sQlo[r * 40 + c8] = *(const uint4*)(g_Qlo + (bh + i0 + r) * ND + c8);
    }
    __syncthreads();

    // A-frag cache: [hi k0, hi k16, lo k0, lo k16]
    uint32_t aq[4][4];
#pragma unroll
    for (int kk = 0; kk < 2; kk++) {
        ldmatrix_x4(aq[kk][0], aq[kk][1], aq[kk][2], aq[kk][3],
                    uQhi + ((16 * wid + a_row) * 40 + kk * 16 + a_col) * 2);
        ldmatrix_x4(aq[2 + kk][0], aq[2 + kk][1], aq[2 + kk][2], aq[2 + kk][3],
                    uQlo + ((16 * wid + a_row) * 40 + kk * 16 + a_col) * 2);
    }

    float m[2] = {-1e30f, -1e30f}, l[2] = {0.f, 0.f};
    float oacc[4][4];
#pragma unroll
    for (int i = 0; i < 4; i++)
#pragma unroll
        for (int j = 0; j < 4; j++) oacc[i][j] = 0.f;

    for (int jt = 0; jt < 16; jt++) {
        const int j0 = jt * 64;
        __syncthreads();
        // stage K
        {
            int r = tid >> 2, c8 = (tid & 3) * 8;
            *(uint4*)&sKhi[r * 40 + c8] = *(const uint4*)(g_Khi + (bh + j0 + r) * ND + c8);
            *(uint4*)&sKlo[r * 40 + c8] = *(const uint4*)(g_Klo + (bh + j0 + r) * ND + c8);
        }
        // stage V transposed
        {
            int j = tid >> 2, d8 = (tid & 3) * 8;
            uint4 vh = *(const uint4*)(g_Vhi + (bh + j0 + j) * ND + d8);
            uint4 vl = *(const uint4*)(g_Vlo + (bh + j0 + j) * ND + d8);
            const __nv_bfloat16* eh = (const __nv_bfloat16*)&vh;
            const __nv_bfloat16* el = (const __nv_bfloat16*)&vl;
#pragma unroll
            for (int u = 0; u < 8; u++) {
                sVhi[(d8 + u) * 72 + j] = eh[u];
                sVlo[(d8 + u) * 72 + j] = el[u];
            }
        }
        // stage Er slice
        {
            int s0 = j0 - i0 + 896;
            for (int it = tid; it < 768; it += 256) {
                int r = it >> 2, c8 = (it & 3) * 8;
                *(uint4*)&sEhi[r * 40 + c8] = *(const uint4*)(g_Erhi + (size_t)(s0 + r) * ND + c8);
                *(uint4*)&sElo[r * 40 + c8] = *(const uint4*)(g_Erlo + (size_t)(s0 + r) * ND + c8);
            }
        }
        __syncthreads();

        // ---- scores ----
        float sacc[8][4], racc[10][4];
#pragma unroll
        for (int i = 0; i < 8; i++)
#pragma unroll
            for (int j = 0; j < 4; j++) sacc[i][j] = 0.f;
#pragma unroll
        for (int i = 0; i < 10; i++)
#pragma unroll
            for (int j = 0; j < 4; j++) racc[i][j] = 0.f;

#pragma unroll
        for (int seg = 0; seg < 3; seg++) {
            const uint32_t uK = (seg == 1) ? uKlo : uKhi;
            const uint32_t uE = (seg == 1) ? uElo : uEhi;
            const int ai = (seg == 2) ? 2 : 0;
#pragma unroll
            for (int kk = 0; kk < 2; kk++) {
                const int kc = kk * 16;
                const uint32_t* A = aq[ai + kk];
#pragma unroll
                for (int nb = 0; nb < 4; nb++) {
                    uint32_t b0, b1, b2, b3;
                    ldmatrix_x4(b0, b1, b2, b3, uK + ((nb * 16 + b_row) * 40 + kc + b_col) * 2);
                    mma_bf16(sacc[nb * 2], A, b0, b1);
                    mma_bf16(sacc[nb * 2 + 1], A, b2, b3);
                }
#pragma unroll
                for (int nb = 0; nb < 5; nb++) {
                    uint32_t b0, b1, b2, b3;
                    ldmatrix_x4(b0, b1, b2, b3,
                                uE + ((ebase + nb * 16 + b_row) * 40 + kc + b_col) * 2);
                    mma_bf16(racc[nb * 2], A, b0, b1);
                    mma_bf16(racc[nb * 2 + 1], A, b2, b3);
                }
            }
        }

        // ---- skew fold Srel into scores (warp-private region of sR) ----
        __syncwarp();
#pragma unroll
        for (int nf = 0; nf < 10; nf++)
#pragma unroll
            for (int e = 0; e < 4; e++) {
                int il = r0 + (e >> 1) * 8;
                int u  = nf * 8 + cq + (e & 1);
                int jj = u + il - 15;
                if (jj >= 0 && jj < 64) sR[(16 * wid + il) * 72 + jj] = racc[nf][e];
            }
        __syncwarp();
#pragma unroll
        for (int nf = 0; nf < 8; nf++) {
            float2 v0 = *(const float2*)&sR[(16 * wid + r0) * 72 + nf * 8 + cq];
            float2 v1 = *(const float2*)&sR[(16 * wid + r0 + 8) * 72 + nf * 8 + cq];
            sacc[nf][0] += v0.x; sacc[nf][1] += v0.y;
            sacc[nf][2] += v1.x; sacc[nf][3] += v1.y;
        }

        // ---- online softmax (rows r0, r0+8; quad = 4 lanes per row) ----
#pragma unroll
        for (int rr = 0; rr < 2; rr++) {
            float mx = sacc[0][rr * 2];
#pragma unroll
            for (int nf = 0; nf < 8; nf++)
                mx = fmaxf(mx, fmaxf(sacc[nf][rr * 2], sacc[nf][rr * 2 + 1]));
            mx = fmaxf(mx, __shfl_xor_sync(0xffffffffu, mx, 1));
            mx = fmaxf(mx, __shfl_xor_sync(0xffffffffu, mx, 2));
            float mn = fmaxf(m[rr], mx);
            float corr = __expf(m[rr] - mn);
            float ps = 0.f;
#pragma unroll
            for (int nf = 0; nf < 8; nf++) {
                sacc[nf][rr * 2]     = __expf(sacc[nf][rr * 2] - mn);
                sacc[nf][rr * 2 + 1] = __expf(sacc[nf][rr * 2 + 1] - mn);
                ps += sacc[nf][rr * 2] + sacc[nf][rr * 2 + 1];
            }
            ps += __shfl_xor_sync(0xffffffffu, ps, 1);
            ps += __shfl_xor_sync(0xffffffffu, ps, 2);
            l[rr] = l[rr] * corr + ps;
            m[rr] = mn;
#pragma unroll
            for (int nf = 0; nf < 4; nf++) {
                oacc[nf][rr * 2]     *= corr;
                oacc[nf][rr * 2 + 1] *= corr;
            }
        }

        // ---- pack P as bf16 hi/lo A-frags (c-frag layout == a-frag layout) ----
        uint32_t aphi[4][4], aplo[4][4];
#pragma unroll
        for (int t = 0; t < 4; t++)
#pragma unroll
            for (int half = 0; half < 2; half++) {
                const int nf = 2 * t + half;
                const float p0 = sacc[nf][0], p1 = sacc[nf][1];
                const float p2 = sacc[nf][2], p3 = sacc[nf][3];
                aphi[t][half * 2]     = cvt2bf(p0, p1);
                aphi[t][half * 2 + 1] = cvt2bf(p2, p3);
                aplo[t][half * 2]     = cvt2bf(bfres(p0), bfres(p1));
                aplo[t][half * 2 + 1] = cvt2bf(bfres(p2), bfres(p3));
            }

        // ---- O += P @ V  (3 passes: hi*hi, hi*lo, lo*hi) ----
#pragma unroll
        for (int pass = 0; pass < 3; pass++) {
            const uint32_t uV = (pass == 1) ? uVlo : uVhi;
#pragma unroll
            for (int t = 0; t < 4; t++) {
                const uint32_t* A = (pass == 2) ? aplo[t] : aphi[t];
#pragma unroll
                for (int nb = 0; nb < 2; nb++) {
                    uint32_t b0, b1, b2, b3;
                    ldmatrix_x4(b0, b1, b2, b3, uV + ((nb * 16 + b_row) * 72 + t * 16 + b_col) * 2);
                    mma_bf16(oacc[nb * 2], A, b0, b1);
                    mma_bf16(oacc[nb * 2 + 1], A, b2, b3);
                }
            }
        }
    }

    // ---- output ----
#pragma unroll
    for (int rr = 0; rr < 2; rr++) {
        const float inv = 1.0f / l[rr];
        const int srow = i0 + 16 * wid + r0 + rr * 8;
        float* op = out + ((size_t)(b * NS + srow)) * NE + h * ND + cq;
#pragma unroll
        for (int nf = 0; nf < 4; nf++)
            *(float2*)(op + nf * 8) = make_float2(oacc[nf][rr * 2] * inv,
                                                  oacc[nf][rr * 2 + 1] * inv);
    }
}

// ---------------------------------------------------------------------------
extern "C" void kernel_launch(void* const* d_in, const int* in_sizes, int n_in,
                              void* d_out, int out_size)
{
    const float* x  = (const float*)d_in[0];
    const float* Wq = (const float*)d_in[1];
    const float* Wk = (const float*)d_in[2];
    const float* Wv = (const float*)d_in[3];
    const float* Er = (const float*)d_in[4];
    float* out = (float*)d_out;

    prep_kernel<<<(NB * NS * NE) / 1024, 256>>>(x, 0, NB * NS * NE);
    prep_kernel<<<(NE * NE) / 1024, 256>>>(Wq, 1, NE * NE);
    prep_kernel<<<(NE * NE) / 1024, 256>>>(Wk, 2, NE * NE);
    prep_kernel<<<(NE * NE) / 1024, 256>>>(Wv, 3, NE * NE);
    prep_er<<<(2048 * ND) / 1024, 256>>>(Er);

    dim3 gg(64, 4, 3);
    proj_mma_kernel<<<gg, 256>>>();

    const int asmem = (128 * 40 * 2 + 64 * 40 * 2 + 32 * 72 * 2 + 192 * 40 * 2) * 2
                      + 128 * 72 * 4;   // 107520 B
    cudaFuncSetAttribute(attn_mma_kernel, cudaFuncAttributeMaxDynamicSharedMemorySize, asmem);
    dim3 ga(8, NH, NB);
    attn_mma_kernel<<<ga, 256, asmem>>>(out);
}

// round 13
// speedup vs baseline: 2.0587x; 1.0988x over previous
#include <cuda_runtime.h>
#include <cuda_bf16.h>
#include <cstdint>

#define NB 8
#define NS 1024
#define NE 512
#define NH 16
#define ND 32

// ---------------------------------------------------------------------------
// Scratch (all bf16 hi/lo pairs)
// ---------------------------------------------------------------------------
__device__ __nv_bfloat16 g_Xhi[NB * NS * NE];
__device__ __nv_bfloat16 g_Xlo[NB * NS * NE];
__device__ __nv_bfloat16 g_Whi[3 * NE * NE];
__device__ __nv_bfloat16 g_Wlo[3 * NE * NE];
// head-separated [b][h][s][d]
__device__ __nv_bfloat16 g_Qhi[NB * NH * NS * ND];
__device__ __nv_bfloat16 g_Qlo[NB * NH * NS * ND];
__device__ __nv_bfloat16 g_Khi[NB * NH * NS * ND];
__device__ __nv_bfloat16 g_Klo[NB * NH * NS * ND];
__device__ __nv_bfloat16 g_Vhi[NB * NH * NS * ND];
__device__ __nv_bfloat16 g_Vlo[NB * NH * NS * ND];
// Er padded to 2048 rows (row 2047 zero)
__device__ __nv_bfloat16 g_Erhi[2048 * ND];
__device__ __nv_bfloat16 g_Erlo[2048 * ND];

// ---------------------------------------------------------------------------
// helpers
// ---------------------------------------------------------------------------
__device__ __forceinline__ uint32_t smem_u32(const void* p) {
    uint32_t a;
    asm("{ .reg .u64 t; cvta.to.shared.u64 t, %1; cvt.u32.u64 %0, t; }" : "=r"(a) : "l"(p));
    return a;
}
__device__ __forceinline__ void ldmatrix_x4(uint32_t& r0, uint32_t& r1, uint32_t& r2, uint32_t& r3,
                                            uint32_t addr) {
    asm volatile("ldmatrix.sync.aligned.m8n8.x4.shared.b16 {%0,%1,%2,%3}, [%4];"
                 : "=r"(r0), "=r"(r1), "=r"(r2), "=r"(r3) : "r"(addr));
}
__device__ __forceinline__ void ldmatrix_x4_trans(uint32_t& r0, uint32_t& r1, uint32_t& r2, uint32_t& r3,
                                                  uint32_t addr) {
    asm volatile("ldmatrix.sync.aligned.m8n8.x4.trans.shared.b16 {%0,%1,%2,%3}, [%4];"
                 : "=r"(r0), "=r"(r1), "=r"(r2), "=r"(r3) : "r"(addr));
}
__device__ __forceinline__ void mma_bf16(float* c,
                                         const uint32_t* a,
                                         uint32_t b0, uint32_t b1) {
    asm volatile("mma.sync.aligned.m16n8k16.row.col.f32.bf16.bf16.f32 "
                 "{%0,%1,%2,%3}, {%4,%5,%6,%7}, {%8,%9}, {%0,%1,%2,%3};"
                 : "+f"(c[0]), "+f"(c[1]), "+f"(c[2]), "+f"(c[3])
                 : "r"(a[0]), "r"(a[1]), "r"(a[2]), "r"(a[3]), "r"(b0), "r"(b1));
}
__device__ __forceinline__ uint32_t cvt2bf(float lo, float hi) {
    uint32_t r;
    asm("cvt.rn.bf16x2.f32 %0, %1, %2;" : "=r"(r) : "f"(hi), "f"(lo));
    return r;
}
__device__ __forceinline__ float bfres(float x) {
    return x - __bfloat162float(__float2bfloat16(x));
}
__device__ __forceinline__ void cp16(uint32_t dst, const void* src) {
    asm volatile("cp.async.cg.shared.global [%0], [%1], 16;" :: "r"(dst), "l"(src) : "memory");
}

// ---------------------------------------------------------------------------
// Prep: fp32 -> (hi, lo) bf16 split. which: 0=X, 1..3=Wq/Wk/Wv
// ---------------------------------------------------------------------------
__global__ __launch_bounds__(256)
void prep_kernel(const float* __restrict__ src, int which, int n)
{
    int i = (blockIdx.x * 256 + threadIdx.x) * 4;
    if (i >= n) return;
    __nv_bfloat16* hi;
    __nv_bfloat16* lo;
    if (which == 0) { hi = g_Xhi; lo = g_Xlo; }
    else            { hi = g_Whi + (which - 1) * NE * NE; lo = g_Wlo + (which - 1) * NE * NE; }
    float4 v = *(const float4*)(src + i);
    float vv[4] = {v.x, v.y, v.z, v.w};
    __nv_bfloat16 hh[4], ll[4];
#pragma unroll
    for (int j = 0; j < 4; j++) {
        hh[j] = __float2bfloat16(vv[j]);
        ll[j] = __float2bfloat16(vv[j] - __bfloat162float(hh[j]));
    }
    *(uint2*)(hi + i) = *(uint2*)hh;
    *(uint2*)(lo + i) = *(uint2*)ll;
}

// Er split with zero-padded row 2047
__global__ __launch_bounds__(256)
void prep_er(const float* __restrict__ Er)
{
    int i = (blockIdx.x * 256 + threadIdx.x) * 4;
    if (i >= 2048 * ND) return;
    float4 v = make_float4(0.f, 0.f, 0.f, 0.f);
    if (i < 2047 * ND) v = *(const float4*)(Er + i);
    float vv[4] = {v.x, v.y, v.z, v.w};
    __nv_bfloat16 hh[4], ll[4];
#pragma unroll
    for (int j = 0; j < 4; j++) {
        hh[j] = __float2bfloat16(vv[j]);
        ll[j] = __float2bfloat16(vv[j] - __bfloat162float(hh[j]));
    }
    *(uint2*)(g_Erhi + i) = *(uint2*)hh;
    *(uint2*)(g_Erlo + i) = *(uint2*)ll;
}

// ---------------------------------------------------------------------------
// Projection GEMM via mma.sync bf16x3 (unchanged from round 11).
// ---------------------------------------------------------------------------
__global__ __launch_bounds__(256, 2)
void proj_mma_kernel()
{
    __shared__ __align__(16) __nv_bfloat16 As[2][128 * 40];
    __shared__ __align__(16) __nv_bfloat16 Bs[2][128 * 40];

    const int tid  = threadIdx.x;
    const int wid  = tid >> 5;
    const int lane = tid & 31;
    const int wm   = (wid & 3) * 32;
    const int wn   = (wid >> 2) * 64;

    const int m0 = blockIdx.x * 128;
    const int n0 = blockIdx.y * 128;
    const int z  = blockIdx.z;
    const __nv_bfloat16* Whi = g_Whi + z * NE * NE;
    const __nv_bfloat16* Wlo = g_Wlo + z * NE * NE;

    const int e0 = tid, e1 = tid + 256;
    const int r0s = e0 >> 2, q0s = e0 & 3;
    const int r1s = e1 >> 2, q1s = e1 & 3;

    float acc[2][8][4];
#pragma unroll
    for (int i = 0; i < 2; i++)
#pragma unroll
        for (int j = 0; j < 8; j++)
#pragma unroll
            for (int c = 0; c < 4; c++) acc[i][j][c] = 0.f;

    const int a_row = (lane & 15);
    const int a_col = (lane >> 4) * 8;
    const int b_row = (lane & 7) + (lane >> 4) * 8;
    const int b_col = ((lane >> 3) & 1) * 8;

    const uint32_t as_base = smem_u32(As);
    const uint32_t bs_base = smem_u32(Bs);

    {
        uint4 va0 = *(const uint4*)(g_Xhi + (size_t)(m0 + r0s) * NE + q0s * 8);
        uint4 va1 = *(const uint4*)(g_Xhi + (size_t)(m0 + r1s) * NE + q1s * 8);
        uint4 vb0 = *(const uint4*)(Whi + (size_t)(n0 + r0s) * NE + q0s * 8);
        uint4 vb1 = *(const uint4*)(Whi + (size_t)(n0 + r1s) * NE + q1s * 8);
        *(uint4*)&As[0][r0s * 40 + q0s * 8] = va0;
        *(uint4*)&As[0][r1s * 40 + q1s * 8] = va1;
        *(uint4*)&Bs[0][r0s * 40 + q0s * 8] = vb0;
        *(uint4*)&Bs[0][r1s * 40 + q1s * 8] = vb1;
    }
    __syncthreads();

    for (int it = 0; it < 48; it++) {
        const int cur = it & 1;
        uint4 va0, va1, vb0, vb1;
        if (it + 1 < 48) {
            const int nit = it + 1;
            const int seg = nit >> 4;
            const int k0  = (nit & 15) * 32;
            const __nv_bfloat16* Asrc = (seg < 2) ? g_Xhi : g_Xlo;
            const __nv_bfloat16* Bsrc = (seg == 1) ? Wlo : Whi;
            va0 = *(const uint4*)(Asrc + (size_t)(m0 + r0s) * NE + k0 + q0s * 8);
            va1 = *(const uint4*)(Asrc + (size_t)(m0 + r1s) * NE + k0 + q1s * 8);
            vb0 = *(const uint4*)(Bsrc + (size_t)(n0 + r0s) * NE + k0 + q0s * 8);
            vb1 = *(const uint4*)(Bsrc + (size_t)(n0 + r1s) * NE + k0 + q1s * 8);
        }

        const uint32_t abuf = as_base + cur * (128 * 40 * 2);
        const uint32_t bbuf = bs_base + cur * (128 * 40 * 2);
#pragma unroll
        for (int kc = 0; kc < 32; kc += 16) {
            uint32_t af[2][4];
#pragma unroll
            for (int rf = 0; rf < 2; rf++) {
                uint32_t addr = abuf + ((wm + rf * 16 + a_row) * 40 + kc + a_col) * 2;
                ldmatrix_x4(af[rf][0], af[rf][1], af[rf][2], af[rf][3], addr);
            }
            uint32_t bf[8][2];
#pragma unroll
            for (int nb = 0; nb < 4; nb++) {
                uint32_t addr = bbuf + ((wn + nb * 16 + b_row) * 40 + kc + b_col) * 2;
                ldmatrix_x4(bf[nb * 2][0], bf[nb * 2][1], bf[nb * 2 + 1][0], bf[nb * 2 + 1][1], addr);
            }
#pragma unroll
            for (int rf = 0; rf < 2; rf++)
#pragma unroll
                for (int nf = 0; nf < 8; nf++)
                    mma_bf16(acc[rf][nf], af[rf], bf[nf][0], bf[nf][1]);
        }

        if (it + 1 < 48) {
            const int nxt = cur ^ 1;
            *(uint4*)&As[nxt][r0s * 40 + q0s * 8] = va0;
            *(uint4*)&As[nxt][r1s * 40 + q1s * 8] = va1;
            *(uint4*)&Bs[nxt][r0s * 40 + q0s * 8] = vb0;
            *(uint4*)&Bs[nxt][r1s * 40 + q1s * 8] = vb1;
            __syncthreads();
        }
    }

    const float qs = (z == 0) ? 0.17677669529663687f : 1.0f;
    __nv_bfloat16* Dhi = (z == 0) ? g_Qhi : (z == 1) ? g_Khi : g_Vhi;
    __nv_bfloat16* Dlo = (z == 0) ? g_Qlo : (z == 1) ? g_Klo : g_Vlo;
    const int er = lane >> 2, ec = (lane & 3) * 2;
#pragma unroll
    for (int rf = 0; rf < 2; rf++)
#pragma unroll
        for (int nf = 0; nf < 8; nf++) {
            const int col = n0 + wn + nf * 8 + ec;
            const int hh = col >> 5, d = col & 31;
#pragma unroll
            for (int rr = 0; rr < 2; rr++) {
                const int row = m0 + wm + rf * 16 + er + rr * 8;
                const int bb = row >> 10, s = row & 1023;
                const size_t idx = (((size_t)bb * NH + hh) * NS + s) * ND + d;
                const float v0 = acc[rf][nf][rr * 2] * qs;
                const float v1 = acc[rf][nf][rr * 2 + 1] * qs;
                *(uint32_t*)(Dhi + idx) = cvt2bf(v0, v1);
                *(uint32_t*)(Dlo + idx) = cvt2bf(bfres(v0), bfres(v1));
            }
        }
}

// ---------------------------------------------------------------------------
// Tensor-core attention with cp.async double-buffered staging.
// CTA = (b, h, 128-q), 8 warps x 16 rows, j-tiles of 64.
// smem (bf16 elems): sQhi/sQlo 128*40 each; 2 stage bufs each:
//   Khi 64*40 @0, Klo @2560, Vhi @5120, Vlo @7680, Ehi 192*40 @10240, Elo @17920
// (buf size 25600 elems); then sR 128*72 fp32.
// ---------------------------------------------------------------------------
#define BUF_ELEMS 25600
#define OFF_KHI 0
#define OFF_KLO 2560
#define OFF_VHI 5120
#define OFF_VLO 7680
#define OFF_EHI 10240
#define OFF_ELO 17920

__global__ __launch_bounds__(256)
void attn_mma_kernel(float* __restrict__ out)
{
    extern __shared__ __align__(16) char smem[];
    __nv_bfloat16* sQhi = (__nv_bfloat16*)smem;             // 128*40
    __nv_bfloat16* sQlo = sQhi + 128 * 40;
    __nv_bfloat16* sBuf = sQlo + 128 * 40;                  // 2 * BUF_ELEMS
    float*         sR   = (float*)(sBuf + 2 * BUF_ELEMS);   // 128*72 fp32

    const int tid = threadIdx.x, wid = tid >> 5, lane = tid & 31;
    const int b = blockIdx.z, h = blockIdx.y, i0 = blockIdx.x * 128;
    const size_t bh = (size_t)(b * NH + h) * NS;
    const int s0base = -i0 + 896;

    const int a_row = lane & 15, a_col = (lane >> 4) * 8;
    const int b_row = (lane & 7) + ((lane >> 4) << 3), b_col = ((lane >> 3) & 1) * 8;
    const int vt_row = (lane & 7) + (((lane >> 3) & 1) << 3), vt_col = (lane >> 4) * 8;
    const int r0 = lane >> 2, cq = (lane & 3) * 2;
    const int ebase = 112 - 16 * wid;

    const uint32_t uQhi = smem_u32(sQhi), uQlo = smem_u32(sQlo);
    const uint32_t uBuf0 = smem_u32(sBuf);
    const uint32_t uBuf1 = uBuf0 + BUF_ELEMS * 2;

    // staging: 2560 16B-chunks per tile, 10 per thread
    // c < 512: K (hi/lo), 512..1023: V (hi/lo), 1024..2559: Er (hi/lo)
    auto stage_tile = [&](uint32_t bufb, int j0) {
#pragma unroll
        for (int c0 = 0; c0 < 2560; c0 += 256) {
            const int c = c0 + tid;
            const __nv_bfloat16* src;
            uint32_t dst;
            if (c < 1024) {
                const int isV = c >> 9;
                const int arr = (c >> 8) & 1;
                const int cc = c & 255;
                const int row = cc >> 2, q8 = (cc & 3) * 8;
                const __nv_bfloat16* g = isV ? (arr ? g_Vlo : g_Vhi) : (arr ? g_Klo : g_Khi);
                src = g + (bh + j0 + row) * ND + q8;
                dst = bufb + ((isV ? OFF_VHI : OFF_KHI) + arr * 2560 + row * 40 + q8) * 2;
            } else {
                int cc = c - 1024;
                const int arr = cc >= 768 ? 1 : 0;
                cc -= arr * 768;
                const int row = cc >> 2, q8 = (cc & 3) * 8;
                const __nv_bfloat16* g = arr ? g_Erlo : g_Erhi;
                src = g + (size_t)(s0base + j0 + row) * ND + q8;
                dst = bufb + ((arr ? OFF_ELO : OFF_EHI) + row * 40 + q8) * 2;
            }
            cp16(dst, src);
        }
    };

    // stage Q (plain, once)
    for (int it = tid; it < 512; it += 256) {
        int r = it >> 2, c8 = (it & 3) * 8;
        *(uint4*)&sQhi[r * 40 + c8] = *(const uint4*)(g_Qhi + (bh + i0 + r) * ND + c8);
        *(uint4*)&sQlo[r * 40 + c8] = *(const uint4*)(g_Qlo + (bh + i0 + r) * ND + c8);
    }
    // prologue: stage tile 0 into buf 0
    stage_tile(uBuf0, 0);
    asm volatile("cp.async.commit_group;" ::: "memory");
    __syncthreads();

    // A-frag cache: [hi k0, hi k16, lo k0, lo k16]
    uint32_t aq[4][4];
#pragma unroll
    for (int kk = 0; kk < 2; kk++) {
        ldmatrix_x4(aq[kk][0], aq[kk][1], aq[kk][2], aq[kk][3],
                    uQhi + ((16 * wid + a_row) * 40 + kk * 16 + a_col) * 2);
        ldmatrix_x4(aq[2 + kk][0], aq[2 + kk][1], aq[2 + kk][2], aq[2 + kk][3],
                    uQlo + ((16 * wid + a_row) * 40 + kk * 16 + a_col) * 2);
    }

    float m[2] = {-1e30f, -1e30f}, l[2] = {0.f, 0.f};
    float oacc[4][4];
#pragma unroll
    for (int i = 0; i < 4; i++)
#pragma unroll
        for (int j = 0; j < 4; j++) oacc[i][j] = 0.f;

    for (int jt = 0; jt < 16; jt++) {
        const uint32_t bufb = (jt & 1) ? uBuf1 : uBuf0;
        __syncthreads();   // (A) all warps done computing on the other buffer
        if (jt < 15) {
            stage_tile((jt & 1) ? uBuf0 : uBuf1, (jt + 1) * 64);
            asm volatile("cp.async.commit_group;" ::: "memory");
            asm volatile("cp.async.wait_group 1;" ::: "memory");
        } else {
            asm volatile("cp.async.wait_group 0;" ::: "memory");
        }
        __syncthreads();   // (B) current tile visible to all

        const uint32_t uKhi = bufb + OFF_KHI * 2, uKlo = bufb + OFF_KLO * 2;
        const uint32_t uVhi = bufb + OFF_VHI * 2, uVlo = bufb + OFF_VLO * 2;
        const uint32_t uEhi = bufb + OFF_EHI * 2, uElo = bufb + OFF_ELO * 2;

        // ---- QK scores ----
        float sacc[8][4];
#pragma unroll
        for (int i = 0; i < 8; i++)
#pragma unroll
            for (int j = 0; j < 4; j++) sacc[i][j] = 0.f;

#pragma unroll
        for (int seg = 0; seg < 3; seg++) {
            const uint32_t uK = (seg == 1) ? uKlo : uKhi;
            const int ai = (seg == 2) ? 2 : 0;
#pragma unroll
            for (int kk = 0; kk < 2; kk++) {
                const uint32_t* A = aq[ai + kk];
#pragma unroll
                for (int nb = 0; nb < 4; nb++) {
                    uint32_t b0, b1, b2, b3;
                    ldmatrix_x4(b0, b1, b2, b3,
                                uK + ((nb * 16 + b_row) * 40 + kk * 16 + b_col) * 2);
                    mma_bf16(sacc[nb * 2], A, b0, b1);
                    mma_bf16(sacc[nb * 2 + 1], A, b2, b3);
                }
            }
        }

        // ---- Srel per n-block: compute + scatter (warp-private sR rows) ----
#pragma unroll
        for (int nb = 0; nb < 5; nb++) {
            float racc2[2][4];
#pragma unroll
            for (int i = 0; i < 2; i++)
#pragma unroll
                for (int j = 0; j < 4; j++) racc2[i][j] = 0.f;
#pragma unroll
            for (int seg = 0; seg < 3; seg++) {
                const uint32_t uE = (seg == 1) ? uElo : uEhi;
                const int ai = (seg == 2) ? 2 : 0;
#pragma unroll
                for (int kk = 0; kk < 2; kk++) {
                    uint32_t b0, b1, b2, b3;
                    ldmatrix_x4(b0, b1, b2, b3,
                                uE + ((ebase + nb * 16 + b_row) * 40 + kk * 16 + b_col) * 2);
                    mma_bf16(racc2[0], aq[ai + kk], b0, b1);
                    mma_bf16(racc2[1], aq[ai + kk], b2, b3);
                }
            }
#pragma unroll
            for (int half = 0; half < 2; half++)
#pragma unroll
                for (int e = 0; e < 4; e++) {
                    int il = r0 + (e >> 1) * 8;
                    int u  = nb * 16 + half * 8 + cq + (e & 1);
                    int jj = u + il - 15;
                    if (jj >= 0 && jj < 64) sR[(16 * wid + il) * 72 + jj] = racc2[half][e];
                }
        }
        __syncwarp();
#pragma unroll
        for (int nf = 0; nf < 8; nf++) {
            float2 v0 = *(const float2*)&sR[(16 * wid + r0) * 72 + nf * 8 + cq];
            float2 v1 = *(const float2*)&sR[(16 * wid + r0 + 8) * 72 + nf * 8 + cq];
            sacc[nf][0] += v0.x; sacc[nf][1] += v0.y;
            sacc[nf][2] += v1.x; sacc[nf][3] += v1.y;
        }

        // ---- online softmax (rows r0, r0+8) ----
#pragma unroll
        for (int rr = 0; rr < 2; rr++) {
            float mx = sacc[0][rr * 2];
#pragma unroll
            for (int nf = 0; nf < 8; nf++)
                mx = fmaxf(mx, fmaxf(sacc[nf][rr * 2], sacc[nf][rr * 2 + 1]));
            mx = fmaxf(mx, __shfl_xor_sync(0xffffffffu, mx, 1));
            mx = fmaxf(mx, __shfl_xor_sync(0xffffffffu, mx, 2));
            float mn = fmaxf(m[rr], mx);
            float corr = __expf(m[rr] - mn);
            float ps = 0.f;
#pragma unroll
            for (int nf = 0; nf < 8; nf++) {
                sacc[nf][rr * 2]     = __expf(sacc[nf][rr * 2] - mn);
                sacc[nf][rr * 2 + 1] = __expf(sacc[nf][rr * 2 + 1] - mn);
                ps += sacc[nf][rr * 2] + sacc[nf][rr * 2 + 1];
            }
            ps += __shfl_xor_sync(0xffffffffu, ps, 1);
            ps += __shfl_xor_sync(0xffffffffu, ps, 2);
            l[rr] = l[rr] * corr + ps;
            m[rr] = mn;
#pragma unroll
            for (int nf = 0; nf < 4; nf++) {
                oacc[nf][rr * 2]     *= corr;
                oacc[nf][rr * 2 + 1] *= corr;
            }
        }

        // ---- pack P as bf16 hi/lo A-frags ----
        uint32_t aphi[4][4], aplo[4][4];
#pragma unroll
        for (int t = 0; t < 4; t++)
#pragma unroll
            for (int half = 0; half < 2; half++) {
                const int nf = 2 * t + half;
                const float p0 = sacc[nf][0], p1 = sacc[nf][1];
                const float p2 = sacc[nf][2], p3 = sacc[nf][3];
                aphi[t][half * 2]     = cvt2bf(p0, p1);
                aphi[t][half * 2 + 1] = cvt2bf(p2, p3);
                aplo[t][half * 2]     = cvt2bf(bfres(p0), bfres(p1));
                aplo[t][half * 2 + 1] = cvt2bf(bfres(p2), bfres(p3));
            }

        // ---- O += P @ V  (V row-major, ldmatrix.trans; 3 passes) ----
#pragma unroll
        for (int pass = 0; pass < 3; pass++) {
            const uint32_t uV = (pass == 1) ? uVlo : uVhi;
#pragma unroll
            for (int t = 0; t < 4; t++) {
                const uint32_t* A = (pass == 2) ? aplo[t] : aphi[t];
#pragma unroll
                for (int nb = 0; nb < 2; nb++) {
                    uint32_t b0, b1, b2, b3;
                    ldmatrix_x4_trans(b0, b1, b2, b3,
                                      uV + ((t * 16 + vt_row) * 40 + nb * 16 + vt_col) * 2);
                    mma_bf16(oacc[nb * 2], A, b0, b1);
                    mma_bf16(oacc[nb * 2 + 1], A, b2, b3);
                }
            }
        }
    }

    // ---- output ----
#pragma unroll
    for (int rr = 0; rr < 2; rr++) {
        const float inv = 1.0f / l[rr];
        const int srow = i0 + 16 * wid + r0 + rr * 8;
        float* op = out + ((size_t)(b * NS + srow)) * NE + h * ND + cq;
#pragma unroll
        for (int nf = 0; nf < 4; nf++)
            *(float2*)(op + nf * 8) = make_float2(oacc[nf][rr * 2] * inv,
                                                  oacc[nf][rr * 2 + 1] * inv);
    }
}

// ---------------------------------------------------------------------------
extern "C" void kernel_launch(void* const* d_in, const int* in_sizes, int n_in,
                              void* d_out, int out_size)
{
    const float* x  = (const float*)d_in[0];
    const float* Wq = (const float*)d_in[1];
    const float* Wk = (const float*)d_in[2];
    const float* Wv = (const float*)d_in[3];
    const float* Er = (const float*)d_in[4];
    float* out = (float*)d_out;

    prep_kernel<<<(NB * NS * NE) / 1024, 256>>>(x, 0, NB * NS * NE);
    prep_kernel<<<(NE * NE) / 1024, 256>>>(Wq, 1, NE * NE);
    prep_kernel<<<(NE * NE) / 1024, 256>>>(Wk, 2, NE * NE);
    prep_kernel<<<(NE * NE) / 1024, 256>>>(Wv, 3, NE * NE);
    prep_er<<<(2048 * ND) / 1024, 256>>>(Er);

    dim3 gg(64, 4, 3);
    proj_mma_kernel<<<gg, 256>>>();

    const int asmem = (128 * 40 * 2 + 2 * BUF_ELEMS) * 2 + 128 * 72 * 4;  // 159744 B
    cudaFuncSetAttribute(attn_mma_kernel, cudaFuncAttributeMaxDynamicSharedMemorySize, asmem);
    dim3 ga(8, NH, NB);
    attn_mma_kernel<<<ga, 256, asmem>>>(out);
}

// round 14
// speedup vs baseline: 2.0954x; 1.0179x over previous
#include <cuda_runtime.h>
#include <cuda_bf16.h>
#include <cstdint>

#define NB 8
#define NS 1024
#define NE 512
#define NH 16
#define ND 32

// ---------------------------------------------------------------------------
// Scratch (all bf16 hi/lo pairs)
// ---------------------------------------------------------------------------
__device__ __nv_bfloat16 g_Xhi[NB * NS * NE];
__device__ __nv_bfloat16 g_Xlo[NB * NS * NE];
__device__ __nv_bfloat16 g_Whi[3 * NE * NE];
__device__ __nv_bfloat16 g_Wlo[3 * NE * NE];
// head-separated [b][h][s][d]
__device__ __nv_bfloat16 g_Qhi[NB * NH * NS * ND];
__device__ __nv_bfloat16 g_Qlo[NB * NH * NS * ND];
__device__ __nv_bfloat16 g_Khi[NB * NH * NS * ND];
__device__ __nv_bfloat16 g_Klo[NB * NH * NS * ND];
__device__ __nv_bfloat16 g_Vhi[NB * NH * NS * ND];
__device__ __nv_bfloat16 g_Vlo[NB * NH * NS * ND];
// Er padded to 2048 rows (row 2047 zero)
__device__ __nv_bfloat16 g_Erhi[2048 * ND];
__device__ __nv_bfloat16 g_Erlo[2048 * ND];

// ---------------------------------------------------------------------------
// helpers
// ---------------------------------------------------------------------------
__device__ __forceinline__ uint32_t smem_u32(const void* p) {
    uint32_t a;
    asm("{ .reg .u64 t; cvta.to.shared.u64 t, %1; cvt.u32.u64 %0, t; }" : "=r"(a) : "l"(p));
    return a;
}
__device__ __forceinline__ void ldmatrix_x4(uint32_t& r0, uint32_t& r1, uint32_t& r2, uint32_t& r3,
                                            uint32_t addr) {
    asm volatile("ldmatrix.sync.aligned.m8n8.x4.shared.b16 {%0,%1,%2,%3}, [%4];"
                 : "=r"(r0), "=r"(r1), "=r"(r2), "=r"(r3) : "r"(addr));
}
__device__ __forceinline__ void ldmatrix_x4_trans(uint32_t& r0, uint32_t& r1, uint32_t& r2, uint32_t& r3,
                                                  uint32_t addr) {
    asm volatile("ldmatrix.sync.aligned.m8n8.x4.trans.shared.b16 {%0,%1,%2,%3}, [%4];"
                 : "=r"(r0), "=r"(r1), "=r"(r2), "=r"(r3) : "r"(addr));
}
__device__ __forceinline__ void mma_bf16(float* c,
                                         const uint32_t* a,
                                         uint32_t b0, uint32_t b1) {
    asm volatile("mma.sync.aligned.m16n8k16.row.col.f32.bf16.bf16.f32 "
                 "{%0,%1,%2,%3}, {%4,%5,%6,%7}, {%8,%9}, {%0,%1,%2,%3};"
                 : "+f"(c[0]), "+f"(c[1]), "+f"(c[2]), "+f"(c[3])
                 : "r"(a[0]), "r"(a[1]), "r"(a[2]), "r"(a[3]), "r"(b0), "r"(b1));
}
__device__ __forceinline__ uint32_t cvt2bf(float lo, float hi) {
    uint32_t r;
    asm("cvt.rn.bf16x2.f32 %0, %1, %2;" : "=r"(r) : "f"(hi), "f"(lo));
    return r;
}
__device__ __forceinline__ float bfres(float x) {
    return x - __bfloat162float(__float2bfloat16(x));
}
__device__ __forceinline__ void cp16(uint32_t dst, const void* src) {
    asm volatile("cp.async.cg.shared.global [%0], [%1], 16;" :: "r"(dst), "l"(src) : "memory");
}

// ---------------------------------------------------------------------------
// Prep: fp32 -> (hi, lo) bf16 split. which: 0=X, 1..3=Wq/Wk/Wv
// ---------------------------------------------------------------------------
__global__ __launch_bounds__(256)
void prep_kernel(const float* __restrict__ src, int which, int n)
{
    int i = (blockIdx.x * 256 + threadIdx.x) * 4;
    if (i >= n) return;
    __nv_bfloat16* hi;
    __nv_bfloat16* lo;
    if (which == 0) { hi = g_Xhi; lo = g_Xlo; }
    else            { hi = g_Whi + (which - 1) * NE * NE; lo = g_Wlo + (which - 1) * NE * NE; }
    float4 v = *(const float4*)(src + i);
    float vv[4] = {v.x, v.y, v.z, v.w};
    __nv_bfloat16 hh[4], ll[4];
#pragma unroll
    for (int j = 0; j < 4; j++) {
        hh[j] = __float2bfloat16(vv[j]);
        ll[j] = __float2bfloat16(vv[j] - __bfloat162float(hh[j]));
    }
    *(uint2*)(hi + i) = *(uint2*)hh;
    *(uint2*)(lo + i) = *(uint2*)ll;
}

// Er split with zero-padded row 2047
__global__ __launch_bounds__(256)
void prep_er(const float* __restrict__ Er)
{
    int i = (blockIdx.x * 256 + threadIdx.x) * 4;
    if (i >= 2048 * ND) return;
    float4 v = make_float4(0.f, 0.f, 0.f, 0.f);
    if (i < 2047 * ND) v = *(const float4*)(Er + i);
    float vv[4] = {v.x, v.y, v.z, v.w};
    __nv_bfloat16 hh[4], ll[4];
#pragma unroll
    for (int j = 0; j < 4; j++) {
        hh[j] = __float2bfloat16(vv[j]);
        ll[j] = __float2bfloat16(vv[j] - __bfloat162float(hh[j]));
    }
    *(uint2*)(g_Erhi + i) = *(uint2*)hh;
    *(uint2*)(g_Erlo + i) = *(uint2*)ll;
}

// ---------------------------------------------------------------------------
// Projection GEMM via mma.sync bf16x3 (unchanged from round 11).
// ---------------------------------------------------------------------------
__global__ __launch_bounds__(256, 2)
void proj_mma_kernel()
{
    __shared__ __align__(16) __nv_bfloat16 As[2][128 * 40];
    __shared__ __align__(16) __nv_bfloat16 Bs[2][128 * 40];

    const int tid  = threadIdx.x;
    const int wid  = tid >> 5;
    const int lane = tid & 31;
    const int wm   = (wid & 3) * 32;
    const int wn   = (wid >> 2) * 64;

    const int m0 = blockIdx.x * 128;
    const int n0 = blockIdx.y * 128;
    const int z  = blockIdx.z;
    const __nv_bfloat16* Whi = g_Whi + z * NE * NE;
    const __nv_bfloat16* Wlo = g_Wlo + z * NE * NE;

    const int e0 = tid, e1 = tid + 256;
    const int r0s = e0 >> 2, q0s = e0 & 3;
    const int r1s = e1 >> 2, q1s = e1 & 3;

    float acc[2][8][4];
#pragma unroll
    for (int i = 0; i < 2; i++)
#pragma unroll
        for (int j = 0; j < 8; j++)
#pragma unroll
            for (int c = 0; c < 4; c++) acc[i][j][c] = 0.f;

    const int a_row = (lane & 15);
    const int a_col = (lane >> 4) * 8;
    const int b_row = (lane & 7) + (lane >> 4) * 8;
    const int b_col = ((lane >> 3) & 1) * 8;

    const uint32_t as_base = smem_u32(As);
    const uint32_t bs_base = smem_u32(Bs);

    {
        uint4 va0 = *(const uint4*)(g_Xhi + (size_t)(m0 + r0s) * NE + q0s * 8);
        uint4 va1 = *(const uint4*)(g_Xhi + (size_t)(m0 + r1s) * NE + q1s * 8);
        uint4 vb0 = *(const uint4*)(Whi + (size_t)(n0 + r0s) * NE + q0s * 8);
        uint4 vb1 = *(const uint4*)(Whi + (size_t)(n0 + r1s) * NE + q1s * 8);
        *(uint4*)&As[0][r0s * 40 + q0s * 8] = va0;
        *(uint4*)&As[0][r1s * 40 + q1s * 8] = va1;
        *(uint4*)&Bs[0][r0s * 40 + q0s * 8] = vb0;
        *(uint4*)&Bs[0][r1s * 40 + q1s * 8] = vb1;
    }
    __syncthreads();

    for (int it = 0; it < 48; it++) {
        const int cur = it & 1;
        uint4 va0, va1, vb0, vb1;
        if (it + 1 < 48) {
            const int nit = it + 1;
            const int seg = nit >> 4;
            const int k0  = (nit & 15) * 32;
            const __nv_bfloat16* Asrc = (seg < 2) ? g_Xhi : g_Xlo;
            const __nv_bfloat16* Bsrc = (seg == 1) ? Wlo : Whi;
            va0 = *(const uint4*)(Asrc + (size_t)(m0 + r0s) * NE + k0 + q0s * 8);
            va1 = *(const uint4*)(Asrc + (size_t)(m0 + r1s) * NE + k0 + q1s * 8);
            vb0 = *(const uint4*)(Bsrc + (size_t)(n0 + r0s) * NE + k0 + q0s * 8);
            vb1 = *(const uint4*)(Bsrc + (size_t)(n0 + r1s) * NE + k0 + q1s * 8);
        }

        const uint32_t abuf = as_base + cur * (128 * 40 * 2);
        const uint32_t bbuf = bs_base + cur * (128 * 40 * 2);
#pragma unroll
        for (int kc = 0; kc < 32; kc += 16) {
            uint32_t af[2][4];
#pragma unroll
            for (int rf = 0; rf < 2; rf++) {
                uint32_t addr = abuf + ((wm + rf * 16 + a_row) * 40 + kc + a_col) * 2;
                ldmatrix_x4(af[rf][0], af[rf][1], af[rf][2], af[rf][3], addr);
            }
            uint32_t bf[8][2];
#pragma unroll
            for (int nb = 0; nb < 4; nb++) {
                uint32_t addr = bbuf + ((wn + nb * 16 + b_row) * 40 + kc + b_col) * 2;
                ldmatrix_x4(bf[nb * 2][0], bf[nb * 2][1], bf[nb * 2 + 1][0], bf[nb * 2 + 1][1], addr);
            }
#pragma unroll
            for (int rf = 0; rf < 2; rf++)
#pragma unroll
                for (int nf = 0; nf < 8; nf++)
                    mma_bf16(acc[rf][nf], af[rf], bf[nf][0], bf[nf][1]);
        }

        if (it + 1 < 48) {
            const int nxt = cur ^ 1;
            *(uint4*)&As[nxt][r0s * 40 + q0s * 8] = va0;
            *(uint4*)&As[nxt][r1s * 40 + q1s * 8] = va1;
            *(uint4*)&Bs[nxt][r0s * 40 + q0s * 8] = vb0;
            *(uint4*)&Bs[nxt][r1s * 40 + q1s * 8] = vb1;
            __syncthreads();
        }
    }

    const float qs = (z == 0) ? 0.17677669529663687f : 1.0f;
    __nv_bfloat16* Dhi = (z == 0) ? g_Qhi : (z == 1) ? g_Khi : g_Vhi;
    __nv_bfloat16* Dlo = (z == 0) ? g_Qlo : (z == 1) ? g_Klo : g_Vlo;
    const int er = lane >> 2, ec = (lane & 3) * 2;
#pragma unroll
    for (int rf = 0; rf < 2; rf++)
#pragma unroll
        for (int nf = 0; nf < 8; nf++) {
            const int col = n0 + wn + nf * 8 + ec;
            const int hh = col >> 5, d = col & 31;
#pragma unroll
            for (int rr = 0; rr < 2; rr++) {
                const int row = m0 + wm + rf * 16 + er + rr * 8;
                const int bb = row >> 10, s = row & 1023;
                const size_t idx = (((size_t)bb * NH + hh) * NS + s) * ND + d;
                const float v0 = acc[rf][nf][rr * 2] * qs;
                const float v1 = acc[rf][nf][rr * 2 + 1] * qs;
                *(uint32_t*)(Dhi + idx) = cvt2bf(v0, v1);
                *(uint32_t*)(Dlo + idx) = cvt2bf(bfres(v0), bfres(v1));
            }
        }
}

// ---------------------------------------------------------------------------
// Tensor-core attention, cp.async double-buffered, precision segs fused so
// each hi B-fragment is loaded ONCE (ldsm 78 -> 52 per warp-tile).
// ---------------------------------------------------------------------------
#define BUF_ELEMS 25600
#define OFF_KHI 0
#define OFF_KLO 2560
#define OFF_VHI 5120
#define OFF_VLO 7680
#define OFF_EHI 10240
#define OFF_ELO 17920

__global__ __launch_bounds__(256)
void attn_mma_kernel(float* __restrict__ out)
{
    extern __shared__ __align__(16) char smem[];
    __nv_bfloat16* sQhi = (__nv_bfloat16*)smem;             // 128*40
    __nv_bfloat16* sQlo = sQhi + 128 * 40;
    __nv_bfloat16* sBuf = sQlo + 128 * 40;                  // 2 * BUF_ELEMS
    float*         sR   = (float*)(sBuf + 2 * BUF_ELEMS);   // 128*72 fp32

    const int tid = threadIdx.x, wid = tid >> 5, lane = tid & 31;
    const int b = blockIdx.z, h = blockIdx.y, i0 = blockIdx.x * 128;
    const size_t bh = (size_t)(b * NH + h) * NS;
    const int s0base = -i0 + 896;

    const int a_row = lane & 15, a_col = (lane >> 4) * 8;
    const int b_row = (lane & 7) + ((lane >> 4) << 3), b_col = ((lane >> 3) & 1) * 8;
    const int vt_row = (lane & 7) + (((lane >> 3) & 1) << 3), vt_col = (lane >> 4) * 8;
    const int r0 = lane >> 2, cq = (lane & 3) * 2;
    const int ebase = 112 - 16 * wid;

    const uint32_t uQhi = smem_u32(sQhi), uQlo = smem_u32(sQlo);
    const uint32_t uBuf0 = smem_u32(sBuf);
    const uint32_t uBuf1 = uBuf0 + BUF_ELEMS * 2;

    auto stage_tile = [&](uint32_t bufb, int j0) {
#pragma unroll
        for (int c0 = 0; c0 < 2560; c0 += 256) {
            const int c = c0 + tid;
            const __nv_bfloat16* src;
            uint32_t dst;
            if (c < 1024) {
                const int isV = c >> 9;
                const int arr = (c >> 8) & 1;
                const int cc = c & 255;
                const int row = cc >> 2, q8 = (cc & 3) * 8;
                const __nv_bfloat16* g = isV ? (arr ? g_Vlo : g_Vhi) : (arr ? g_Klo : g_Khi);
                src = g + (bh + j0 + row) * ND + q8;
                dst = bufb + ((isV ? OFF_VHI : OFF_KHI) + arr * 2560 + row * 40 + q8) * 2;
            } else {
                int cc = c - 1024;
                const int arr = cc >= 768 ? 1 : 0;
                cc -= arr * 768;
                const int row = cc >> 2, q8 = (cc & 3) * 8;
                const __nv_bfloat16* g = arr ? g_Erlo : g_Erhi;
                src = g + (size_t)(s0base + j0 + row) * ND + q8;
                dst = bufb + ((arr ? OFF_ELO : OFF_EHI) + row * 40 + q8) * 2;
            }
            cp16(dst, src);
        }
    };

    // stage Q (plain, once)
    for (int it = tid; it < 512; it += 256) {
        int r = it >> 2, c8 = (it & 3) * 8;
        *(uint4*)&sQhi[r * 40 + c8] = *(const uint4*)(g_Qhi + (bh + i0 + r) * ND + c8);
        *(uint4*)&sQlo[r * 40 + c8] = *(const uint4*)(g_Qlo + (bh + i0 + r) * ND + c8);
    }
    stage_tile(uBuf0, 0);
    asm volatile("cp.async.commit_group;" ::: "memory");
    __syncthreads();

    // A-frag cache: [hi k0, hi k16, lo k0, lo k16]
    uint32_t aq[4][4];
#pragma unroll
    for (int kk = 0; kk < 2; kk++) {
        ldmatrix_x4(aq[kk][0], aq[kk][1], aq[kk][2], aq[kk][3],
                    uQhi + ((16 * wid + a_row) * 40 + kk * 16 + a_col) * 2);
        ldmatrix_x4(aq[2 + kk][0], aq[2 + kk][1], aq[2 + kk][2], aq[2 + kk][3],
                    uQlo + ((16 * wid + a_row) * 40 + kk * 16 + a_col) * 2);
    }

    float m[2] = {-1e30f, -1e30f}, l[2] = {0.f, 0.f};
    float oacc[4][4];
#pragma unroll
    for (int i = 0; i < 4; i++)
#pragma unroll
        for (int j = 0; j < 4; j++) oacc[i][j] = 0.f;

    for (int jt = 0; jt < 16; jt++) {
        const uint32_t bufb = (jt & 1) ? uBuf1 : uBuf0;
        __syncthreads();   // (A) all warps done computing on the other buffer
        if (jt < 15) {
            stage_tile((jt & 1) ? uBuf0 : uBuf1, (jt + 1) * 64);
            asm volatile("cp.async.commit_group;" ::: "memory");
            asm volatile("cp.async.wait_group 1;" ::: "memory");
        } else {
            asm volatile("cp.async.wait_group 0;" ::: "memory");
        }
        __syncthreads();   // (B) current tile visible to all

        const uint32_t uKhi = bufb + OFF_KHI * 2, uKlo = bufb + OFF_KLO * 2;
        const uint32_t uVhi = bufb + OFF_VHI * 2, uVlo = bufb + OFF_VLO * 2;
        const uint32_t uEhi = bufb + OFF_EHI * 2, uElo = bufb + OFF_ELO * 2;

        // ---- QK scores: per B-frag, fuse 3 precision segs (6 MMA / 2 ldsm) --
        float sacc[8][4];
#pragma unroll
        for (int i = 0; i < 8; i++)
#pragma unroll
            for (int j = 0; j < 4; j++) sacc[i][j] = 0.f;

#pragma unroll
        for (int kk = 0; kk < 2; kk++) {
            const uint32_t* Ahi = aq[kk];
            const uint32_t* Alo = aq[2 + kk];
#pragma unroll
            for (int nb = 0; nb < 4; nb++) {
                uint32_t h0, h1, h2, h3, l0, l1, l2, l3;
                ldmatrix_x4(h0, h1, h2, h3,
                            uKhi + ((nb * 16 + b_row) * 40 + kk * 16 + b_col) * 2);
                ldmatrix_x4(l0, l1, l2, l3,
                            uKlo + ((nb * 16 + b_row) * 40 + kk * 16 + b_col) * 2);
                mma_bf16(sacc[nb * 2], Ahi, h0, h1);
                mma_bf16(sacc[nb * 2 + 1], Ahi, h2, h3);
                mma_bf16(sacc[nb * 2], Alo, h0, h1);
                mma_bf16(sacc[nb * 2 + 1], Alo, h2, h3);
                mma_bf16(sacc[nb * 2], Ahi, l0, l1);
                mma_bf16(sacc[nb * 2 + 1], Ahi, l2, l3);
            }
        }

        // ---- Srel per n-block (fused segs) + scatter -------------------------
#pragma unroll
        for (int nb = 0; nb < 5; nb++) {
            float racc2[2][4];
#pragma unroll
            for (int i = 0; i < 2; i++)
#pragma unroll
                for (int j = 0; j < 4; j++) racc2[i][j] = 0.f;
#pragma unroll
            for (int kk = 0; kk < 2; kk++) {
                const uint32_t* Ahi = aq[kk];
                const uint32_t* Alo = aq[2 + kk];
                uint32_t h0, h1, h2, h3, l0, l1, l2, l3;
                ldmatrix_x4(h0, h1, h2, h3,
                            uEhi + ((ebase + nb * 16 + b_row) * 40 + kk * 16 + b_col) * 2);
                ldmatrix_x4(l0, l1, l2, l3,
                            uElo + ((ebase + nb * 16 + b_row) * 40 + kk * 16 + b_col) * 2);
                mma_bf16(racc2[0], Ahi, h0, h1);
                mma_bf16(racc2[1], Ahi, h2, h3);
                mma_bf16(racc2[0], Alo, h0, h1);
                mma_bf16(racc2[1], Alo, h2, h3);
                mma_bf16(racc2[0], Ahi, l0, l1);
                mma_bf16(racc2[1], Ahi, l2, l3);
            }
#pragma unroll
            for (int half = 0; half < 2; half++)
#pragma unroll
                for (int e = 0; e < 4; e++) {
                    int il = r0 + (e >> 1) * 8;
                    int u  = nb * 16 + half * 8 + cq + (e & 1);
                    int jj = u + il - 15;
                    if (jj >= 0 && jj < 64) sR[(16 * wid + il) * 72 + jj] = racc2[half][e];
                }
        }
        __syncwarp();
#pragma unroll
        for (int nf = 0; nf < 8; nf++) {
            float2 v0 = *(const float2*)&sR[(16 * wid + r0) * 72 + nf * 8 + cq];
            float2 v1 = *(const float2*)&sR[(16 * wid + r0 + 8) * 72 + nf * 8 + cq];
            sacc[nf][0] += v0.x; sacc[nf][1] += v0.y;
            sacc[nf][2] += v1.x; sacc[nf][3] += v1.y;
        }

        // ---- online softmax (rows r0, r0+8) ----
#pragma unroll
        for (int rr = 0; rr < 2; rr++) {
            float mx = sacc[0][rr * 2];
#pragma unroll
            for (int nf = 0; nf < 8; nf++)
                mx = fmaxf(mx, fmaxf(sacc[nf][rr * 2], sacc[nf][rr * 2 + 1]));
            mx = fmaxf(mx, __shfl_xor_sync(0xffffffffu, mx, 1));
            mx = fmaxf(mx, __shfl_xor_sync(0xffffffffu, mx, 2));
            float mn = fmaxf(m[rr], mx);
            float corr = __expf(m[rr] - mn);
            float ps = 0.f;
#pragma unroll
            for (int nf = 0; nf < 8; nf++) {
                sacc[nf][rr * 2]     = __expf(sacc[nf][rr * 2] - mn);
                sacc[nf][rr * 2 + 1] = __expf(sacc[nf][rr * 2 + 1] - mn);
                ps += sacc[nf][rr * 2] + sacc[nf][rr * 2 + 1];
            }
            ps += __shfl_xor_sync(0xffffffffu, ps, 1);
            ps += __shfl_xor_sync(0xffffffffu, ps, 2);
            l[rr] = l[rr] * corr + ps;
            m[rr] = mn;
#pragma unroll
            for (int nf = 0; nf < 4; nf++) {
                oacc[nf][rr * 2]     *= corr;
                oacc[nf][rr * 2 + 1] *= corr;
            }
        }

        // ---- pack P as bf16 hi/lo A-frags ----
        uint32_t aphi[4][4], aplo[4][4];
#pragma unroll
        for (int t = 0; t < 4; t++)
#pragma unroll
            for (int half = 0; half < 2; half++) {
                const int nf = 2 * t + half;
                const float p0 = sacc[nf][0], p1 = sacc[nf][1];
                const float p2 = sacc[nf][2], p3 = sacc[nf][3];
                aphi[t][half * 2]     = cvt2bf(p0, p1);
                aphi[t][half * 2 + 1] = cvt2bf(p2, p3);
                aplo[t][half * 2]     = cvt2bf(bfres(p0), bfres(p1));
                aplo[t][half * 2 + 1] = cvt2bf(bfres(p2), bfres(p3));
            }

        // ---- O += P @ V: per V-frag, fuse 3 passes (6 MMA / 2 ldsm) ----------
#pragma unroll
        for (int t = 0; t < 4; t++) {
#pragma unroll
            for (int nb = 0; nb < 2; nb++) {
                uint32_t h0, h1, h2, h3, l0, l1, l2, l3;
                ldmatrix_x4_trans(h0, h1, h2, h3,
                                  uVhi + ((t * 16 + vt_row) * 40 + nb * 16 + vt_col) * 2);
                ldmatrix_x4_trans(l0, l1, l2, l3,
                                  uVlo + ((t * 16 + vt_row) * 40 + nb * 16 + vt_col) * 2);
                mma_bf16(oacc[nb * 2], aphi[t], h0, h1);
                mma_bf16(oacc[nb * 2 + 1], aphi[t], h2, h3);
                mma_bf16(oacc[nb * 2], aplo[t], h0, h1);
                mma_bf16(oacc[nb * 2 + 1], aplo[t], h2, h3);
                mma_bf16(oacc[nb * 2], aphi[t], l0, l1);
                mma_bf16(oacc[nb * 2 + 1], aphi[t], l2, l3);
            }
        }
    }

    // ---- output ----
#pragma unroll
    for (int rr = 0; rr < 2; rr++) {
        const float inv = 1.0f / l[rr];
        const int srow = i0 + 16 * wid + r0 + rr * 8;
        float* op = out + ((size_t)(b * NS + srow)) * NE + h * ND + cq;
#pragma unroll
        for (int nf = 0; nf < 4; nf++)
            *(float2*)(op + nf * 8) = make_float2(oacc[nf][rr * 2] * inv,
                                                  oacc[nf][rr * 2 + 1] * inv);
    }
}

// ---------------------------------------------------------------------------
extern "C" void kernel_launch(void* const* d_in, const int* in_sizes, int n_in,
                              void* d_out, int out_size)
{
    const float* x  = (const float*)d_in[0];
    const float* Wq = (const float*)d_in[1];
    const float* Wk = (const float*)d_in[2];
    const float* Wv = (const float*)d_in[3];
    const float* Er = (const float*)d_in[4];
    float* out = (float*)d_out;

    prep_kernel<<<(NB * NS * NE) / 1024, 256>>>(x, 0, NB * NS * NE);
    prep_kernel<<<(NE * NE) / 1024, 256>>>(Wq, 1, NE * NE);
    prep_kernel<<<(NE * NE) / 1024, 256>>>(Wk, 2, NE * NE);
    prep_kernel<<<(NE * NE) / 1024, 256>>>(Wv, 3, NE * NE);
    prep_er<<<(2048 * ND) / 1024, 256>>>(Er);

    dim3 gg(64, 4, 3);
    proj_mma_kernel<<<gg, 256>>>();

    const int asmem = (128 * 40 * 2 + 2 * BUF_ELEMS) * 2 + 128 * 72 * 4;  // 159744 B
    cudaFuncSetAttribute(attn_mma_kernel, cudaFuncAttributeMaxDynamicSharedMemorySize, asmem);
    dim3 ga(8, NH, NB);
    attn_mma_kernel<<<ga, 256, asmem>>>(out);
}

// round 17
// speedup vs baseline: 2.3635x; 1.1279x over previous
#include <cuda_runtime.h>
#include <cuda_bf16.h>
#include <cstdint>

#define NB 8
#define NS 1024
#define NE 512
#define NH 16
#define ND 32

// ---------------------------------------------------------------------------
// Scratch (all bf16 hi/lo pairs)
// ---------------------------------------------------------------------------
__device__ __nv_bfloat16 g_Xhi[NB * NS * NE];
__device__ __nv_bfloat16 g_Xlo[NB * NS * NE];
__device__ __nv_bfloat16 g_Whi[3 * NE * NE];
__device__ __nv_bfloat16 g_Wlo[3 * NE * NE];
// head-separated [b][h][s][d]
__device__ __nv_bfloat16 g_Qhi[NB * NH * NS * ND];
__device__ __nv_bfloat16 g_Qlo[NB * NH * NS * ND];
__device__ __nv_bfloat16 g_Khi[NB * NH * NS * ND];
__device__ __nv_bfloat16 g_Klo[NB * NH * NS * ND];
__device__ __nv_bfloat16 g_Vhi[NB * NH * NS * ND];
__device__ __nv_bfloat16 g_Vlo[NB * NH * NS * ND];
// Er padded to 2048 rows (row 2047 zero)
__device__ __nv_bfloat16 g_Erhi[2048 * ND];
__device__ __nv_bfloat16 g_Erlo[2048 * ND];

// ---------------------------------------------------------------------------
// helpers
// ---------------------------------------------------------------------------
__device__ __forceinline__ uint32_t smem_u32(const void* p) {
    uint32_t a;
    asm("{ .reg .u64 t; cvta.to.shared.u64 t, %1; cvt.u32.u64 %0, t; }" : "=r"(a) : "l"(p));
    return a;
}
__device__ __forceinline__ void ldmatrix_x4(uint32_t& r0, uint32_t& r1, uint32_t& r2, uint32_t& r3,
                                            uint32_t addr) {
    asm volatile("ldmatrix.sync.aligned.m8n8.x4.shared.b16 {%0,%1,%2,%3}, [%4];"
                 : "=r"(r0), "=r"(r1), "=r"(r2), "=r"(r3) : "r"(addr));
}
__device__ __forceinline__ void ldmatrix_x4_trans(uint32_t& r0, uint32_t& r1, uint32_t& r2, uint32_t& r3,
                                                  uint32_t addr) {
    asm volatile("ldmatrix.sync.aligned.m8n8.x4.trans.shared.b16 {%0,%1,%2,%3}, [%4];"
                 : "=r"(r0), "=r"(r1), "=r"(r2), "=r"(r3) : "r"(addr));
}
__device__ __forceinline__ void mma_bf16(float* c,
                                         const uint32_t* a,
                                         uint32_t b0, uint32_t b1) {
    asm volatile("mma.sync.aligned.m16n8k16.row.col.f32.bf16.bf16.f32 "
                 "{%0,%1,%2,%3}, {%4,%5,%6,%7}, {%8,%9}, {%0,%1,%2,%3};"
                 : "+f"(c[0]), "+f"(c[1]), "+f"(c[2]), "+f"(c[3])
                 : "r"(a[0]), "r"(a[1]), "r"(a[2]), "r"(a[3]), "r"(b0), "r"(b1));
}
__device__ __forceinline__ uint32_t cvt2bf(float lo, float hi) {
    uint32_t r;
    asm("cvt.rn.bf16x2.f32 %0, %1, %2;" : "=r"(r) : "f"(hi), "f"(lo));
    return r;
}
__device__ __forceinline__ float bfres(float x) {
    return x - __bfloat162float(__float2bfloat16(x));
}
__device__ __forceinline__ void cp16(uint32_t dst, const void* src) {
    asm volatile("cp.async.cg.shared.global [%0], [%1], 16;" :: "r"(dst), "l"(src) : "memory");
}

// ---------------------------------------------------------------------------
// Prep: fp32 -> (hi, lo) bf16 split. which: 0=X, 1..3=Wq/Wk/Wv
// ---------------------------------------------------------------------------
__global__ __launch_bounds__(256)
void prep_kernel(const float* __restrict__ src, int which, int n)
{
    int i = (blockIdx.x * 256 + threadIdx.x) * 4;
    if (i >= n) return;
    __nv_bfloat16* hi;
    __nv_bfloat16* lo;
    if (which == 0) { hi = g_Xhi; lo = g_Xlo; }
    else            { hi = g_Whi + (which - 1) * NE * NE; lo = g_Wlo + (which - 1) * NE * NE; }
    float4 v = *(const float4*)(src + i);
    float vv[4] = {v.x, v.y, v.z, v.w};
    __nv_bfloat16 hh[4], ll[4];
#pragma unroll
    for (int j = 0; j < 4; j++) {
        hh[j] = __float2bfloat16(vv[j]);
        ll[j] = __float2bfloat16(vv[j] - __bfloat162float(hh[j]));
    }
    *(uint2*)(hi + i) = *(uint2*)hh;
    *(uint2*)(lo + i) = *(uint2*)ll;
}

// Er split with zero-padded row 2047
__global__ __launch_bounds__(256)
void prep_er(const float* __restrict__ Er)
{
    int i = (blockIdx.x * 256 + threadIdx.x) * 4;
    if (i >= 2048 * ND) return;
    float4 v = make_float4(0.f, 0.f, 0.f, 0.f);
    if (i < 2047 * ND) v = *(const float4*)(Er + i);
    float vv[4] = {v.x, v.y, v.z, v.w};
    __nv_bfloat16 hh[4], ll[4];
#pragma unroll
    for (int j = 0; j < 4; j++) {
        hh[j] = __float2bfloat16(vv[j]);
        ll[j] = __float2bfloat16(vv[j] - __bfloat162float(hh[j]));
    }
    *(uint2*)(g_Erhi + i) = *(uint2*)hh;
    *(uint2*)(g_Erlo + i) = *(uint2*)ll;
}

// ---------------------------------------------------------------------------
// Projection GEMM via mma.sync bf16x3 (unchanged from round 11).
// ---------------------------------------------------------------------------
__global__ __launch_bounds__(256, 2)
void proj_mma_kernel()
{
    __shared__ __align__(16) __nv_bfloat16 As[2][128 * 40];
    __shared__ __align__(16) __nv_bfloat16 Bs[2][128 * 40];

    const int tid  = threadIdx.x;
    const int wid  = tid >> 5;
    const int lane = tid & 31;
    const int wm   = (wid & 3) * 32;
    const int wn   = (wid >> 2) * 64;

    const int m0 = blockIdx.x * 128;
    const int n0 = blockIdx.y * 128;
    const int z  = blockIdx.z;
    const __nv_bfloat16* Whi = g_Whi + z * NE * NE;
    const __nv_bfloat16* Wlo = g_Wlo + z * NE * NE;

    const int e0 = tid, e1 = tid + 256;
    const int r0s = e0 >> 2, q0s = e0 & 3;
    const int r1s = e1 >> 2, q1s = e1 & 3;

    float acc[2][8][4];
#pragma unroll
    for (int i = 0; i < 2; i++)
#pragma unroll
        for (int j = 0; j < 8; j++)
#pragma unroll
            for (int c = 0; c < 4; c++) acc[i][j][c] = 0.f;

    const int a_row = (lane & 15);
    const int a_col = (lane >> 4) * 8;
    const int b_row = (lane & 7) + (lane >> 4) * 8;
    const int b_col = ((lane >> 3) & 1) * 8;

    const uint32_t as_base = smem_u32(As);
    const uint32_t bs_base = smem_u32(Bs);

    {
        uint4 va0 = *(const uint4*)(g_Xhi + (size_t)(m0 + r0s) * NE + q0s * 8);
        uint4 va1 = *(const uint4*)(g_Xhi + (size_t)(m0 + r1s) * NE + q1s * 8);
        uint4 vb0 = *(const uint4*)(Whi + (size_t)(n0 + r0s) * NE + q0s * 8);
        uint4 vb1 = *(const uint4*)(Whi + (size_t)(n0 + r1s) * NE + q1s * 8);
        *(uint4*)&As[0][r0s * 40 + q0s * 8] = va0;
        *(uint4*)&As[0][r1s * 40 + q1s * 8] = va1;
        *(uint4*)&Bs[0][r0s * 40 + q0s * 8] = vb0;
        *(uint4*)&Bs[0][r1s * 40 + q1s * 8] = vb1;
    }
    __syncthreads();

    for (int it = 0; it < 48; it++) {
        const int cur = it & 1;
        uint4 va0, va1, vb0, vb1;
        if (it + 1 < 48) {
            const int nit = it + 1;
            const int seg = nit >> 4;
            const int k0  = (nit & 15) * 32;
            const __nv_bfloat16* Asrc = (seg < 2) ? g_Xhi : g_Xlo;
            const __nv_bfloat16* Bsrc = (seg == 1) ? Wlo : Whi;
            va0 = *(const uint4*)(Asrc + (size_t)(m0 + r0s) * NE + k0 + q0s * 8);
            va1 = *(const uint4*)(Asrc + (size_t)(m0 + r1s) * NE + k0 + q1s * 8);
            vb0 = *(const uint4*)(Bsrc + (size_t)(n0 + r0s) * NE + k0 + q0s * 8);
            vb1 = *(const uint4*)(Bsrc + (size_t)(n0 + r1s) * NE + k0 + q1s * 8);
        }

        const uint32_t abuf = as_base + cur * (128 * 40 * 2);
        const uint32_t bbuf = bs_base + cur * (128 * 40 * 2);
#pragma unroll
        for (int kc = 0; kc < 32; kc += 16) {
            uint32_t af[2][4];
#pragma unroll
            for (int rf = 0; rf < 2; rf++) {
                uint32_t addr = abuf + ((wm + rf * 16 + a_row) * 40 + kc + a_col) * 2;
                ldmatrix_x4(af[rf][0], af[rf][1], af[rf][2], af[rf][3], addr);
            }
            uint32_t bf[8][2];
#pragma unroll
            for (int nb = 0; nb < 4; nb++) {
                uint32_t addr = bbuf + ((wn + nb * 16 + b_row) * 40 + kc + b_col) * 2;
                ldmatrix_x4(bf[nb * 2][0], bf[nb * 2][1], bf[nb * 2 + 1][0], bf[nb * 2 + 1][1], addr);
            }
#pragma unroll
            for (int rf = 0; rf < 2; rf++)
#pragma unroll
                for (int nf = 0; nf < 8; nf++)
                    mma_bf16(acc[rf][nf], af[rf], bf[nf][0], bf[nf][1]);
        }

        if (it + 1 < 48) {
            const int nxt = cur ^ 1;
            *(uint4*)&As[nxt][r0s * 40 + q0s * 8] = va0;
            *(uint4*)&As[nxt][r1s * 40 + q1s * 8] = va1;
            *(uint4*)&Bs[nxt][r0s * 40 + q0s * 8] = vb0;
            *(uint4*)&Bs[nxt][r1s * 40 + q1s * 8] = vb1;
            __syncthreads();
        }
    }

    const float qs = (z == 0) ? 0.17677669529663687f : 1.0f;
    __nv_bfloat16* Dhi = (z == 0) ? g_Qhi : (z == 1) ? g_Khi : g_Vhi;
    __nv_bfloat16* Dlo = (z == 0) ? g_Qlo : (z == 1) ? g_Klo : g_Vlo;
    const int er = lane >> 2, ec = (lane & 3) * 2;
#pragma unroll
    for (int rf = 0; rf < 2; rf++)
#pragma unroll
        for (int nf = 0; nf < 8; nf++) {
            const int col = n0 + wn + nf * 8 + ec;
            const int hh = col >> 5, d = col & 31;
#pragma unroll
            for (int rr = 0; rr < 2; rr++) {
                const int row = m0 + wm + rf * 16 + er + rr * 8;
                const int bb = row >> 10, s = row & 1023;
                const size_t idx = (((size_t)bb * NH + hh) * NS + s) * ND + d;
                const float v0 = acc[rf][nf][rr * 2] * qs;
                const float v1 = acc[rf][nf][rr * 2 + 1] * qs;
                *(uint32_t*)(Dhi + idx) = cvt2bf(v0, v1);
                *(uint32_t*)(Dlo + idx) = cvt2bf(bfres(v0), bfres(v1));
            }
        }
}

// ---------------------------------------------------------------------------
// Tensor-core attention, slim smem (106.5 KB -> 2 CTAs/SM):
//  - Er as 192-row ring, staging only 64 new rows/tile (mid-tile, post-Srel)
//  - sR overlaps the dead sQ region (Q lives in regs after prologue)
//  - K/V cp.async double-buffered as before
// ---------------------------------------------------------------------------
#define REG0 17408
#define KVBUF 10240
#define OFF_KHI 0
#define OFF_KLO 2560
#define OFF_VHI 5120
#define OFF_VLO 7680
#define ER_OFF 37888
#define ER_LO 7680

__global__ __launch_bounds__(256, 2)
void attn_mma_kernel(float* __restrict__ out)
{
    extern __shared__ __align__(16) char smem[];
    __nv_bfloat16* sQhi = (__nv_bfloat16*)smem;             // 128*40 (dies after prologue)
    __nv_bfloat16* sQlo = sQhi + 128 * 40;
    float*         sR   = (float*)smem;                     // 128*68 fp32, overlaps Q

    const int tid = threadIdx.x, wid = tid >> 5, lane = tid & 31;
    const int b = blockIdx.z, h = blockIdx.y, i0 = blockIdx.x * 128;
    const size_t bh = (size_t)(b * NH + h) * NS;
    const int s0base = 896 - i0;                            // in [0, 896], 64-aligned

    const int a_row = lane & 15, a_col = (lane >> 4) * 8;
    const int b_row = (lane & 7) + ((lane >> 4) << 3), b_col = ((lane >> 3) & 1) * 8;
    const int vt_row = (lane & 7) + (((lane >> 3) & 1) << 3), vt_col = (lane >> 4) * 8;
    const int r0 = lane >> 2, cq = (lane & 3) * 2;
    const int ebase = 112 - 16 * wid;

    const uint32_t uQhi = smem_u32(sQhi), uQlo = smem_u32(sQlo);
    const uint32_t ubase = uQhi;
    const uint32_t uBuf0 = ubase + REG0 * 2;
    const uint32_t uBuf1 = uBuf0 + KVBUF * 2;
    const uint32_t uEr   = ubase + ER_OFF * 2;

    // K/V staging: 1024 16B chunks, 4 per thread
    auto stage_kv = [&](uint32_t bufb, int j0) {
#pragma unroll
        for (int c0 = 0; c0 < 1024; c0 += 256) {
            const int c = c0 + tid;
            const int isV = c >> 9;
            const int arr = (c >> 8) & 1;
            const int cc = c & 255;
            const int row = cc >> 2, q8 = (cc & 3) * 8;
            const __nv_bfloat16* g = isV ? (arr ? g_Vlo : g_Vhi) : (arr ? g_Klo : g_Khi);
            cp16(bufb + ((isV ? OFF_VHI : OFF_KHI) + arr * 2560 + row * 40 + q8) * 2,
                 g + (bh + j0 + row) * ND + q8);
        }
    };
    // Er staging: nrows rows from absolute row sAbs into ring slots (sAbs+r) mod 192.
    auto stage_er = [&](int sAbs, int sMod, int nrows) {
        const int half = nrows * 4;
        for (int c = tid; c < half * 2; c += 256) {
            const int arr = c >= half;
            const int cc = arr ? c - half : c;
            const int row = cc >> 2, q8 = (cc & 3) * 8;
            int slot = sMod + row; if (slot >= 192) slot -= 192;
            const __nv_bfloat16* g = arr ? g_Erlo : g_Erhi;
            cp16(uEr + (arr * ER_LO + slot * 40 + q8) * 2,
                 g + (size_t)(sAbs + row) * ND + q8);
        }
    };

    // ---- prologue ----
    for (int it = tid; it < 512; it += 256) {
        int r = it >> 2, c8 = (it & 3) * 8;
        *(uint4*)&sQhi[r * 40 + c8] = *(const uint4*)(g_Qhi + (bh + i0 + r) * ND + c8);
        *(uint4*)&sQlo[r * 40 + c8] = *(const uint4*)(g_Qlo + (bh + i0 + r) * ND + c8);
    }
    stage_kv(uBuf0, 0);
    asm volatile("cp.async.commit_group;" ::: "memory");      // group KV_0
    const int sMod0 = s0base % 192;
    stage_er(s0base, sMod0, 192);
    asm volatile("cp.async.commit_group;" ::: "memory");      // group ER_0
    __syncthreads();   // Q plain stores visible

    // A-frag cache: [hi k0, hi k16, lo k0, lo k16]  (sQ dead afterwards)
    uint32_t aq[4][4];
#pragma unroll
    for (int kk = 0; kk < 2; kk++) {
        ldmatrix_x4(aq[kk][0], aq[kk][1], aq[kk][2], aq[kk][3],
                    uQhi + ((16 * wid + a_row) * 40 + kk * 16 + a_col) * 2);
        ldmatrix_x4(aq[2 + kk][0], aq[2 + kk][1], aq[2 + kk][2], aq[2 + kk][3],
                    uQlo + ((16 * wid + a_row) * 40 + kk * 16 + a_col) * 2);
    }

    float m[2] = {-1e30f, -1e30f}, l[2] = {0.f, 0.f};
    float oacc[4][4];
#pragma unroll
    for (int i = 0; i < 4; i++)
#pragma unroll
        for (int j = 0; j < 4; j++) oacc[i][j] = 0.f;

    int eb0 = sMod0;   // (s0base + 64*jt) mod 192, updated incrementally

    for (int jt = 0; jt < 16; jt++) {
        const uint32_t bufb = (jt & 1) ? uBuf1 : uBuf0;
        __syncthreads();   // (A) prior compute done (V reads, Q/sR reads)
        if (jt < 15) {
            stage_kv((jt & 1) ? uBuf0 : uBuf1, (jt + 1) * 64);
            asm volatile("cp.async.commit_group;" ::: "memory");   // KV_{jt+1}
            asm volatile("cp.async.wait_group 1;" ::: "memory");   // KV_jt + ER_jt done
        } else {
            asm volatile("cp.async.wait_group 0;" ::: "memory");
        }
        __syncthreads();   // (B) current tile visible

        const uint32_t uKhi = bufb + OFF_KHI * 2, uKlo = bufb + OFF_KLO * 2;
        const uint32_t uVhi = bufb + OFF_VHI * 2, uVlo = bufb + OFF_VLO * 2;

        // ---- QK scores (fused precision segs, hi B loaded once) ----
        float sacc[8][4];
#pragma unroll
        for (int i = 0; i < 8; i++)
#pragma unroll
            for (int j = 0; j < 4; j++) sacc[i][j] = 0.f;

#pragma unroll
        for (int kk = 0; kk < 2; kk++) {
            const uint32_t* Ahi = aq[kk];
            const uint32_t* Alo = aq[2 + kk];
#pragma unroll
            for (int nb = 0; nb < 4; nb++) {
                uint32_t h0, h1, h2, h3, l0, l1, l2, l3;
                ldmatrix_x4(h0, h1, h2, h3,
                            uKhi + ((nb * 16 + b_row) * 40 + kk * 16 + b_col) * 2);
                ldmatrix_x4(l0, l1, l2, l3,
                            uKlo + ((nb * 16 + b_row) * 40 + kk * 16 + b_col) * 2);
                mma_bf16(sacc[nb * 2], Ahi, h0, h1);
                mma_bf16(sacc[nb * 2 + 1], Ahi, h2, h3);
                mma_bf16(sacc[nb * 2], Alo, h0, h1);
                mma_bf16(sacc[nb * 2 + 1], Alo, h2, h3);
                mma_bf16(sacc[nb * 2], Ahi, l0, l1);
                mma_bf16(sacc[nb * 2 + 1], Ahi, l2, l3);
            }
        }

        // ---- Srel per n-block (ring-indexed Er) + scatter ----
#pragma unroll
        for (int nb = 0; nb < 5; nb++) {
            int sb = eb0 + ebase + nb * 16;
            if (sb >= 192) sb -= 192;           // 16-aligned, <192 -> block never wraps
            float racc2[2][4];
#pragma unroll
            for (int i = 0; i < 2; i++)
#pragma unroll
                for (int j = 0; j < 4; j++) racc2[i][j] = 0.f;
#pragma unroll
            for (int kk = 0; kk < 2; kk++) {
                const uint32_t* Ahi = aq[kk];
                const uint32_t* Alo = aq[2 + kk];
                uint32_t h0, h1, h2, h3, l0, l1, l2, l3;
                ldmatrix_x4(h0, h1, h2, h3,
                            uEr + ((sb + b_row) * 40 + kk * 16 + b_col) * 2);
                ldmatrix_x4(l0, l1, l2, l3,
                            uEr + (ER_LO + (sb + b_row) * 40 + kk * 16 + b_col) * 2);
                mma_bf16(racc2[0], Ahi, h0, h1);
                mma_bf16(racc2[1], Ahi, h2, h3);
                mma_bf16(racc2[0], Alo, h0, h1);
                mma_bf16(racc2[1], Alo, h2, h3);
                mma_bf16(racc2[0], Ahi, l0, l1);
                mma_bf16(racc2[1], Ahi, l2, l3);
            }
#pragma unroll
            for (int half = 0; half < 2; half++)
#pragma unroll
                for (int e = 0; e < 4; e++) {
                    int il = r0 + (e >> 1) * 8;
                    int u  = nb * 16 + half * 8 + cq + (e & 1);
                    int jj = u + il - 15;
                    if (jj >= 0 && jj < 64) sR[(16 * wid + il) * 68 + jj] = racc2[half][e];
                }
        }
        __syncwarp();
#pragma unroll
        for (int nf = 0; nf < 8; nf++) {
            float2 v0 = *(const float2*)&sR[(16 * wid + r0) * 68 + nf * 8 + cq];
            float2 v1 = *(const float2*)&sR[(16 * wid + r0 + 8) * 68 + nf * 8 + cq];
            sacc[nf][0] += v0.x; sacc[nf][1] += v0.y;
            sacc[nf][2] += v1.x; sacc[nf][3] += v1.y;
        }

        // ---- (C) Er retiring slots now dead everywhere -> prefetch next 64 rows
        __syncthreads();
        if (jt < 15) {
            stage_er(s0base + 64 * jt + 192, eb0, 64);   // (s0base+64jt+192)%192 == eb0
            asm volatile("cp.async.commit_group;" ::: "memory");   // ER_{jt+1}
        }
        eb0 += 64; if (eb0 >= 192) eb0 -= 192;

        // ---- online softmax (rows r0, r0+8) ----
#pragma unroll
        for (int rr = 0; rr < 2; rr++) {
            float mx = sacc[0][rr * 2];
#pragma unroll
            for (int nf = 0; nf < 8; nf++)
                mx = fmaxf(mx, fmaxf(sacc[nf][rr * 2], sacc[nf][rr * 2 + 1]));
            mx = fmaxf(mx, __shfl_xor_sync(0xffffffffu, mx, 1));
            mx = fmaxf(mx, __shfl_xor_sync(0xffffffffu, mx, 2));
            float mn = fmaxf(m[rr], mx);
            float corr = __expf(m[rr] - mn);
            float ps = 0.f;
#pragma unroll
            for (int nf = 0; nf < 8; nf++) {
                sacc[nf][rr * 2]     = __expf(sacc[nf][rr * 2] - mn);
                sacc[nf][rr * 2 + 1] = __expf(sacc[nf][rr * 2 + 1] - mn);
                ps += sacc[nf][rr * 2] + sacc[nf][rr * 2 + 1];
            }
            ps += __shfl_xor_sync(0xffffffffu, ps, 1);
            ps += __shfl_xor_sync(0xffffffffu, ps, 2);
            l[rr] = l[rr] * corr + ps;
            m[rr] = mn;
#pragma unroll
            for (int nf = 0; nf < 4; nf++) {
                oacc[nf][rr * 2]     *= corr;
                oacc[nf][rr * 2 + 1] *= corr;
            }
        }

        // ---- pack P as bf16 hi/lo A-frags ----
        uint32_t aphi[4][4], aplo[4][4];
#pragma unroll
        for (int t = 0; t < 4; t++)
#pragma unroll
            for (int half = 0; half < 2; half++) {
                const int nf = 2 * t + half;
                const float p0 = sacc[nf][0], p1 = sacc[nf][1];
                const float p2 = sacc[nf][2], p3 = sacc[nf][3];
                aphi[t][half * 2]     = cvt2bf(p0, p1);
                aphi[t][half * 2 + 1] = cvt2bf(p2, p3);
                aplo[t][half * 2]     = cvt2bf(bfres(p0), bfres(p1));
                aplo[t][half * 2 + 1] = cvt2bf(bfres(p2), bfres(p3));
            }

        // ---- O += P @ V (fused passes, hi V loaded once) ----
#pragma unroll
        for (int t = 0; t < 4; t++) {
#pragma unroll
            for (int nb = 0; nb < 2; nb++) {
                uint32_t h0, h1, h2, h3, l0, l1, l2, l3;
                ldmatrix_x4_trans(h0, h1, h2, h3,
                                  uVhi + ((t * 16 + vt_row) * 40 + nb * 16 + vt_col) * 2);
                ldmatrix_x4_trans(l0, l1, l2, l3,
                                  uVlo + ((t * 16 + vt_row) * 40 + nb * 16 + vt_col) * 2);
                mma_bf16(oacc[nb * 2], aphi[t], h0, h1);
                mma_bf16(oacc[nb * 2 + 1], aphi[t], h2, h3);
                mma_bf16(oacc[nb * 2], aplo[t], h0, h1);
                mma_bf16(oacc[nb * 2 + 1], aplo[t], h2, h3);
                mma_bf16(oacc[nb * 2], aphi[t], l0, l1);
                mma_bf16(oacc[nb * 2 + 1], aphi[t], l2, l3);
            }
        }
    }

    // ---- output ----
#pragma unroll
    for (int rr = 0; rr < 2; rr++) {
        const float inv = 1.0f / l[rr];
        const int srow = i0 + 16 * wid + r0 + rr * 8;
        float* op = out + ((size_t)(b * NS + srow)) * NE + h * ND + cq;
#pragma unroll
        for (int nf = 0; nf < 4; nf++)
            *(float2*)(op + nf * 8) = make_float2(oacc[nf][rr * 2] * inv,
                                                  oacc[nf][rr * 2 + 1] * inv);
    }
}

// ---------------------------------------------------------------------------
extern "C" void kernel_launch(void* const* d_in, const int* in_sizes, int n_in,
                              void* d_out, int out_size)
{
    const float* x  = (const float*)d_in[0];
    const float* Wq = (const float*)d_in[1];
    const float* Wk = (const float*)d_in[2];
    const float* Wv = (const float*)d_in[3];
    const float* Er = (const float*)d_in[4];
    float* out = (float*)d_out;

    prep_kernel<<<(NB * NS * NE) / 1024, 256>>>(x, 0, NB * NS * NE);
    prep_kernel<<<(NE * NE) / 1024, 256>>>(Wq, 1, NE * NE);
    prep_kernel<<<(NE * NE) / 1024, 256>>>(Wk, 2, NE * NE);
    prep_kernel<<<(NE * NE) / 1024, 256>>>(Wv, 3, NE * NE);
    prep_er<<<(2048 * ND) / 1024, 256>>>(Er);

    dim3 gg(64, 4, 3);
    proj_mma_kernel<<<gg, 256>>>();

    const int asmem = (REG0 + 2 * KVBUF + 2 * 192 * 40) * 2;   // 106496 B
    cudaFuncSetAttribute(attn_mma_kernel, cudaFuncAttributeMaxDynamicSharedMemorySize, asmem);
    dim3 ga(8, NH, NB);
    attn_mma_kernel<<<ga, 256, asmem>>>(out);
}